// round 1
// baseline (speedup 1.0000x reference)
#include <cuda_runtime.h>
#include <math.h>

// Problem constants
#define NTOK   8192      // B*S = 4*2048
#define DIN    1024
#define NT     12        // trees
#define NI     7         // internal nodes
#define NL     8         // leaves
#define NDEC   84        // NT*NI
#define NOUT   96        // 84 decisions + 12 gates
#define DOUTD  1024
#define NHEADS 3

// Kernel A config
#define A_TOK     32
#define A_KT      128
#define A_THREADS 256
#define A_WSTRIDE (A_KT + 2)   // 130 words: keeps 8B alignment, near-conflict-free LDS.64
#define DEC_STRIDE 97

// Kernel B config
#define B_TOK     64
#define B_DT      128
#define B_THREADS 256

// routed scratch, stored transposed: [96][NTOK]
__device__ __align__(16) float g_routed[NOUT * NTOK];

__device__ __forceinline__ void fma2(unsigned long long &acc, unsigned long long a, unsigned long long b) {
    asm volatile("fma.rn.f32x2 %0, %1, %2, %0;" : "+l"(acc) : "l"(a), "l"(b));
}
__device__ __forceinline__ unsigned long long pack2(float lo, float hi) {
    unsigned long long r;
    asm("mov.b64 %0, {%1, %2};" : "=l"(r) : "f"(lo), "f"(hi));
    return r;
}
__device__ __forceinline__ float2 unpack2(unsigned long long v) {
    float2 f;
    asm("mov.b64 {%0, %1}, %2;" : "=f"(f.x), "=f"(f.y) : "l"(v));
    return f;
}

// ---------------------------------------------------------------------------
// Kernel A: per-token decision + gate dots, sigmoid/leaf-prob/softmax epilogue
// writes routed[(t*8+l)][token] (transposed) to g_routed
// ---------------------------------------------------------------------------
__global__ void __launch_bounds__(A_THREADS) kernelA(
    const float* __restrict__ x,     // [NTOK][DIN]
    const float* __restrict__ dw,    // [NT][NI][DIN]
    const float* __restrict__ db,    // [NT][NI]
    const float* __restrict__ ntl,   // [NT][NI]
    const float* __restrict__ gw,    // [NT][DIN]
    const float* __restrict__ gb,    // [NT]
    const int*   __restrict__ pidx,  // [NL][3]
    const float* __restrict__ pdir)  // [NL][3]
{
    extern __shared__ float sm[];
    float* Ws = sm;                        // [NOUT][A_WSTRIDE] = 12480 floats
    float* Xs = sm + NOUT * A_WSTRIDE;     // [A_TOK][A_KT]     = 4096 floats
    __shared__ float s_invt[NDEC];
    __shared__ float s_bias[NDEC];
    __shared__ float s_gb[NT];
    __shared__ int   s_pi[NL * 3];
    __shared__ float s_pd[NL * 3];

    const int tid  = threadIdx.x;
    const int tok0 = blockIdx.x * A_TOK;

    if (tid < NDEC) {
        float t  = ntl[tid] + 0.5413f;
        float sp = (t > 20.f) ? t : log1pf(__expf(t));  // softplus, TEMPERATURE=1
        s_invt[tid] = 1.0f / sp;
        s_bias[tid] = db[tid];
    } else if (tid < NDEC + NT) {
        s_gb[tid - NDEC] = gb[tid - NDEC];
    } else if (tid < NDEC + NT + NL * 3) {
        int i = tid - NDEC - NT;
        s_pi[i] = pidx[i];
        s_pd[i] = pdir[i];
    }

    const int oz = tid & 31;   // outputs oz, oz+32, oz+64
    const int tz = tid >> 5;   // tokens tz*4 .. tz*4+3

    unsigned long long acc[4][3];
    #pragma unroll
    for (int i = 0; i < 4; i++)
        #pragma unroll
        for (int j = 0; j < 3; j++) acc[i][j] = 0ull;

    for (int k0 = 0; k0 < DIN; k0 += A_KT) {
        __syncthreads();
        // stage W: 96 rows x 128 k, as float4 loads -> 2x float2 stores
        #pragma unroll
        for (int it = 0; it < 12; it++) {
            int idx = it * A_THREADS + tid;          // 0..3071
            int o   = idx >> 5;
            int kq  = idx & 31;
            const float* src = (o < NDEC) ? (dw + o * DIN) : (gw + (o - NDEC) * DIN);
            float4 v = *(const float4*)(src + k0 + kq * 4);
            float* dst = Ws + o * A_WSTRIDE + kq * 4;
            *(float2*)(dst)     = make_float2(v.x, v.y);
            *(float2*)(dst + 2) = make_float2(v.z, v.w);
        }
        // stage X: 32 rows x 128 k
        #pragma unroll
        for (int it = 0; it < 4; it++) {
            int idx = it * A_THREADS + tid;          // 0..1023
            int r   = idx >> 5;
            int kq  = idx & 31;
            float4 v = *(const float4*)(x + (size_t)(tok0 + r) * DIN + k0 + kq * 4);
            *(float4*)(Xs + r * A_KT + kq * 4) = v;
        }
        __syncthreads();

        #pragma unroll 4
        for (int k = 0; k < A_KT; k += 2) {
            unsigned long long xv[4], wv[3];
            #pragma unroll
            for (int i = 0; i < 4; i++)
                xv[i] = *(const unsigned long long*)(Xs + (tz * 4 + i) * A_KT + k);
            #pragma unroll
            for (int j = 0; j < 3; j++)
                wv[j] = *(const unsigned long long*)(Ws + (oz + 32 * j) * A_WSTRIDE + k);
            #pragma unroll
            for (int i = 0; i < 4; i++)
                #pragma unroll
                for (int j = 0; j < 3; j++) fma2(acc[i][j], xv[i], wv[j]);
        }
    }

    // reduce f32x2 pairs into Dec (reuses Ws region; stride 97 -> conflict-free reads)
    __syncthreads();
    float* Dec = Ws;  // [A_TOK][DEC_STRIDE]
    #pragma unroll
    for (int i = 0; i < 4; i++)
        #pragma unroll
        for (int j = 0; j < 3; j++) {
            float2 f = unpack2(acc[i][j]);
            Dec[(tz * 4 + i) * DEC_STRIDE + (oz + 32 * j)] = f.x + f.y;
        }
    __syncthreads();

    if (tid < A_TOK) {
        const int token = tok0 + tid;
        const float* d = Dec + tid * DEC_STRIDE;

        // gate softmax over trees
        float g[NT];
        float m = -1e30f;
        #pragma unroll
        for (int t = 0; t < NT; t++) { g[t] = d[NDEC + t] + s_gb[t]; m = fmaxf(m, g[t]); }
        float sum = 0.f;
        #pragma unroll
        for (int t = 0; t < NT; t++) { g[t] = __expf(g[t] - m); sum += g[t]; }
        const float inv = 1.0f / sum;

        #pragma unroll
        for (int t = 0; t < NT; t++) {
            const float w = g[t] * inv;
            float sg[NI];
            #pragma unroll
            for (int n = 0; n < NI; n++) {
                float z = (d[t * NI + n] + s_bias[t * NI + n]) * s_invt[t * NI + n];
                sg[n] = 1.0f / (1.0f + __expf(-z));
            }
            #pragma unroll
            for (int l = 0; l < NL; l++) {
                float p = w;
                #pragma unroll
                for (int dd = 0; dd < 3; dd++) {
                    float sv  = sg[s_pi[l * 3 + dd]];
                    float dir = s_pd[l * 3 + dd];
                    p *= dir * sv + (1.f - dir) * (1.f - sv);
                }
                g_routed[(t * NL + l) * NTOK + token] = p;
            }
        }
    }
}

// ---------------------------------------------------------------------------
// Kernel B: out[h, tok, d] = sum_l routed[l, tok] * LO[h, l, d]
// block: 64 tokens x 128 dims x 1 head; f32x2 packed FMA register tile 8x4
// ---------------------------------------------------------------------------
__global__ void __launch_bounds__(B_THREADS) kernelB(
    const float* __restrict__ lo,   // [NHEADS][NOUT][DOUTD]
    float*       __restrict__ out)  // [NHEADS][NTOK][DOUTD]
{
    extern __shared__ float sm[];
    float* Ls = sm;                   // [NOUT][B_DT]
    float* Rs = sm + NOUT * B_DT;     // [NOUT][B_TOK]

    const int tid  = threadIdx.x;
    const int tok0 = blockIdx.x * B_TOK;
    const int d0   = blockIdx.y * B_DT;
    const int h    = blockIdx.z;

    // stage LO slice: 96 x 128 floats
    const float* lsrc = lo + (size_t)h * NOUT * DOUTD + d0;
    #pragma unroll
    for (int it = 0; it < 12; it++) {
        int idx = it * B_THREADS + tid;
        int r = idx >> 5, cq = idx & 31;
        *(float4*)(Ls + r * B_DT + cq * 4) = *(const float4*)(lsrc + (size_t)r * DOUTD + cq * 4);
    }
    // stage routed slice: 96 x 64 floats (already transposed in global)
    #pragma unroll
    for (int it = 0; it < 6; it++) {
        int idx = it * B_THREADS + tid;
        int r = idx >> 4, cq = idx & 15;
        *(float4*)(Rs + r * B_TOK + cq * 4) = *(const float4*)(g_routed + r * NTOK + tok0 + cq * 4);
    }
    __syncthreads();

    const int dq = tid & 31;   // dims dq*4..+3
    const int tq = tid >> 5;   // tokens tq*8..+7

    unsigned long long acc[8][2];
    #pragma unroll
    for (int i = 0; i < 8; i++) { acc[i][0] = 0ull; acc[i][1] = 0ull; }

    #pragma unroll 2
    for (int l = 0; l < NOUT; l++) {
        float4 lv = *(const float4*)(Ls + l * B_DT + dq * 4);
        unsigned long long lv01 = pack2(lv.x, lv.y);
        unsigned long long lv23 = pack2(lv.z, lv.w);
        float4 ra = *(const float4*)(Rs + l * B_TOK + tq * 8);
        float4 rb = *(const float4*)(Rs + l * B_TOK + tq * 8 + 4);
        float rv[8] = {ra.x, ra.y, ra.z, ra.w, rb.x, rb.y, rb.z, rb.w};
        #pragma unroll
        for (int i = 0; i < 8; i++) {
            unsigned long long rr = pack2(rv[i], rv[i]);
            fma2(acc[i][0], rr, lv01);
            fma2(acc[i][1], rr, lv23);
        }
    }

    float* obase = out + ((size_t)h * NTOK + tok0) * DOUTD + d0 + dq * 4;
    #pragma unroll
    for (int i = 0; i < 8; i++) {
        float2 a = unpack2(acc[i][0]);
        float2 b = unpack2(acc[i][1]);
        float4 v = make_float4(a.x, a.y, b.x, b.y);
        *(float4*)(obase + (size_t)(tq * 8 + i) * DOUTD) = v;
    }
}

// ---------------------------------------------------------------------------
extern "C" void kernel_launch(void* const* d_in, const int* in_sizes, int n_in,
                              void* d_out, int out_size) {
    const float* x    = (const float*)d_in[0];
    const float* dw   = (const float*)d_in[1];
    const float* db   = (const float*)d_in[2];
    const float* ntl  = (const float*)d_in[3];
    const float* gw   = (const float*)d_in[4];
    const float* gb   = (const float*)d_in[5];
    const float* lo   = (const float*)d_in[6];
    const int*   pidx = (const int*)d_in[7];
    const float* pdir = (const float*)d_in[8];
    float* out = (float*)d_out;

    const int smemA = (NOUT * A_WSTRIDE + A_TOK * A_KT) * sizeof(float);   // 66304 B
    const int smemB = (NOUT * B_DT + NOUT * B_TOK) * sizeof(float);        // 73728 B
    cudaFuncSetAttribute(kernelA, cudaFuncAttributeMaxDynamicSharedMemorySize, smemA);
    cudaFuncSetAttribute(kernelB, cudaFuncAttributeMaxDynamicSharedMemorySize, smemB);

    kernelA<<<NTOK / A_TOK, A_THREADS, smemA>>>(x, dw, db, ntl, gw, gb, pidx, pdir);

    dim3 gridB(NTOK / B_TOK, DOUTD / B_DT, NHEADS);
    kernelB<<<gridB, B_THREADS, smemB>>>(lo, out);
}

// round 3
// speedup vs baseline: 1.1603x; 1.1603x over previous
#include <cuda_runtime.h>
#include <cuda_bf16.h>
#include <math.h>
#include <stdint.h>

// Problem constants
#define NTOK   8192
#define DIN    1024
#define NT     12
#define NI     7
#define NL     8
#define NDEC   84
#define NOUT   96
#define DOUTD  1024
#define NHEADS 3

// ---------------- scratch (device globals; no allocs allowed) ----------------
__device__ __align__(16) unsigned short g_rhi[NTOK * NOUT];          // routed hi bf16 [tok][96]
__device__ __align__(16) unsigned short g_rlo[NTOK * NOUT];          // routed lo bf16
__device__ __align__(16) unsigned short g_bhi[NHEADS * DOUTD * NOUT]; // LO^T hi [h][d][l]
__device__ __align__(16) unsigned short g_blo[NHEADS * DOUTD * NOUT]; // LO^T lo

// ---------------- f32x2 helpers (kernel A) ----------------
__device__ __forceinline__ void fma2(unsigned long long &acc, unsigned long long a, unsigned long long b) {
    asm volatile("fma.rn.f32x2 %0, %1, %2, %0;" : "+l"(acc) : "l"(a), "l"(b));
}
__device__ __forceinline__ float2 unpack2(unsigned long long v) {
    float2 f;
    asm("mov.b64 {%0, %1}, %2;" : "=f"(f.x), "=f"(f.y) : "l"(v));
    return f;
}
__device__ __forceinline__ uint32_t smem_u32(const void* p) {
    uint32_t a;
    asm("{ .reg .u64 t; cvta.to.shared.u64 t, %1; cvt.u32.u64 %0, t; }" : "=r"(a) : "l"(p));
    return a;
}
__device__ __forceinline__ void split_bf16(float x, unsigned short &h, unsigned short &l) {
    __nv_bfloat16 hb = __float2bfloat16(x);
    float hf = __bfloat162float(hb);
    __nv_bfloat16 lb = __float2bfloat16(x - hf);
    h = __bfloat16_as_ushort(hb);
    l = __bfloat16_as_ushort(lb);
}

// ---------------- mma.sync / ldmatrix (plain sm_80+ features) ----------------
#define LDSM4(r, addr) \
    asm volatile("ldmatrix.sync.aligned.m8n8.x4.shared.b16 {%0,%1,%2,%3}, [%4];" \
        : "=r"((r)[0]), "=r"((r)[1]), "=r"((r)[2]), "=r"((r)[3]) : "r"(addr))

#define MMA16816(c, a, b0, b1) \
    asm volatile("mma.sync.aligned.m16n8k16.row.col.f32.bf16.bf16.f32 " \
        "{%0,%1,%2,%3}, {%4,%5,%6,%7}, {%8,%9}, {%0,%1,%2,%3};" \
        : "+f"((c)[0]), "+f"((c)[1]), "+f"((c)[2]), "+f"((c)[3]) \
        : "r"((a)[0]), "r"((a)[1]), "r"((a)[2]), "r"((a)[3]), "r"(b0), "r"(b1))

// ---------------------------------------------------------------------------
// Kernel P: transpose leaf_outputs [h][l][d] -> bf16 hi/lo [h][d][l]
// ---------------------------------------------------------------------------
__global__ void __launch_bounds__(256) kernelP(const float* __restrict__ lo) {
    int idx = blockIdx.x * 256 + threadIdx.x;          // 3*96*256
    int dq = idx & 255;
    int t  = idx >> 8;
    int l  = t % NOUT;
    int h  = t / NOUT;
    float4 v = *(const float4*)(lo + ((size_t)(h * NOUT + l) << 10) + dq * 4);
    float vals[4] = {v.x, v.y, v.z, v.w};
    #pragma unroll
    for (int e = 0; e < 4; e++) {
        unsigned short hs, ls;
        split_bf16(vals[e], hs, ls);
        size_t o = (size_t)(h * DOUTD + dq * 4 + e) * NOUT + l;
        g_bhi[o] = hs;
        g_blo[o] = ls;
    }
}

// ---------------------------------------------------------------------------
// Kernel A: routing GEMM + sigmoid/leaf-prob/softmax epilogue -> bf16 hi/lo
//   64 tokens/block, 256 threads, 8 tokens/thread x 3 outs, f32x2 FMA
// ---------------------------------------------------------------------------
#define A_TOK 64
#define A_KT  128
#define A_WS  132
#define DEC_S 97

__global__ void __launch_bounds__(256, 1) kernelA(
    const float* __restrict__ x,
    const float* __restrict__ dw,
    const float* __restrict__ db,
    const float* __restrict__ ntl,
    const float* __restrict__ gw,
    const float* __restrict__ gb,
    const int*   __restrict__ pidx,
    const float* __restrict__ pdir)
{
    extern __shared__ float sm[];
    float* Ws = sm;                       // [96][132]
    float* Xs = sm + NOUT * A_WS;         // [64][128]
    __shared__ float s_invt[NDEC];
    __shared__ float s_bias[NDEC];
    __shared__ float s_gb[NT];
    __shared__ int   s_pi[NL * 3];
    __shared__ float s_pd[NL * 3];

    const int tid  = threadIdx.x;
    const int tok0 = blockIdx.x * A_TOK;
    const int lane = tid & 31;
    const int w    = tid >> 5;

    if (tid < NDEC) {
        float t  = ntl[tid] + 0.5413f;
        float sp = (t > 20.f) ? t : log1pf(__expf(t));
        s_invt[tid] = 1.0f / sp;
        s_bias[tid] = db[tid];
    } else if (tid < NDEC + NT) {
        s_gb[tid - NDEC] = gb[tid - NDEC];
    } else if (tid < NDEC + NT + NL * 3) {
        int i = tid - NDEC - NT;
        s_pi[i] = pidx[i];
        s_pd[i] = pdir[i];
    }

    unsigned long long acc[8][3];
    #pragma unroll
    for (int i = 0; i < 8; i++)
        #pragma unroll
        for (int j = 0; j < 3; j++) acc[i][j] = 0ull;

    for (int k0 = 0; k0 < DIN; k0 += A_KT) {
        __syncthreads();
        #pragma unroll
        for (int it = 0; it < 12; it++) {            // W: 96x128
            int idx = it * 256 + tid;
            int o = idx >> 5, kq = idx & 31;
            const float* src = (o < NDEC) ? (dw + (size_t)o * DIN) : (gw + (size_t)(o - NDEC) * DIN);
            float4 v = *(const float4*)(src + k0 + kq * 4);
            *(float4*)(Ws + o * A_WS + kq * 4) = v;
        }
        #pragma unroll
        for (int it = 0; it < 8; it++) {             // X: 64x128
            int idx = it * 256 + tid;
            int r = idx >> 5, kq = idx & 31;
            float4 v = *(const float4*)(x + (size_t)(tok0 + r) * DIN + k0 + kq * 4);
            *(float4*)(Xs + r * A_KT + kq * 4) = v;
        }
        __syncthreads();

        #pragma unroll 2
        for (int k = 0; k < A_KT; k += 4) {
            ulonglong2 wv[3], xv[8];
            #pragma unroll
            for (int j = 0; j < 3; j++)
                wv[j] = *(const ulonglong2*)(Ws + (lane + 32 * j) * A_WS + k);
            #pragma unroll
            for (int i = 0; i < 8; i++)
                xv[i] = *(const ulonglong2*)(Xs + (w * 8 + i) * A_KT + k);
            #pragma unroll
            for (int i = 0; i < 8; i++)
                #pragma unroll
                for (int j = 0; j < 3; j++) {
                    fma2(acc[i][j], xv[i].x, wv[j].x);
                    fma2(acc[i][j], xv[i].y, wv[j].y);
                }
        }
    }

    __syncthreads();
    float* Dec = sm;   // [64][97]
    #pragma unroll
    for (int i = 0; i < 8; i++)
        #pragma unroll
        for (int j = 0; j < 3; j++) {
            float2 f = unpack2(acc[i][j]);
            Dec[(w * 8 + i) * DEC_S + (lane + 32 * j)] = f.x + f.y;
        }
    __syncthreads();

    if (tid < A_TOK) {
        const int token = tok0 + tid;
        const float* d = Dec + tid * DEC_S;

        float g[NT];
        float m = -1e30f;
        #pragma unroll
        for (int t = 0; t < NT; t++) { g[t] = d[NDEC + t] + s_gb[t]; m = fmaxf(m, g[t]); }
        float sum = 0.f;
        #pragma unroll
        for (int t = 0; t < NT; t++) { g[t] = __expf(g[t] - m); sum += g[t]; }
        const float inv = 1.0f / sum;

        unsigned short* rh = g_rhi + (size_t)token * NOUT;
        unsigned short* rl = g_rlo + (size_t)token * NOUT;

        #pragma unroll
        for (int t = 0; t < NT; t++) {
            const float wgt = g[t] * inv;
            float sg[NI];
            #pragma unroll
            for (int n = 0; n < NI; n++) {
                float z = (d[t * NI + n] + s_bias[t * NI + n]) * s_invt[t * NI + n];
                sg[n] = 1.0f / (1.0f + __expf(-z));
            }
            #pragma unroll
            for (int l = 0; l < NL; l++) {
                float p = wgt;
                #pragma unroll
                for (int dd = 0; dd < 3; dd++) {
                    float sv  = sg[s_pi[l * 3 + dd]];
                    float dir = s_pd[l * 3 + dd];
                    p *= dir * sv + (1.f - dir) * (1.f - sv);
                }
                unsigned short hs, ls;
                split_bf16(p, hs, ls);
                rh[t * NL + l] = hs;
                rl[t * NL + l] = ls;
            }
        }
    }
}

// ---------------------------------------------------------------------------
// Kernel B (HMMA): out[h, 128 tok, 128 d] = routed[128,96] @ LO^T[96,128]
//   bf16 hi/lo 3-term split via mma.sync.m16n8k16 (fp32 accum)
//   8 warps: warp = (wr: 4 tok-groups of 32) x (wc: 2 d-groups of 64)
// ---------------------------------------------------------------------------
#define BT_M 128
#define BT_N 128
#define SST  104                       // shorts per smem row (96 + 8 pad)
#define SSTB (SST * 2)                 // 208 bytes; %16==0, conflict-free LDSM
#define SMEM_B_BYTES (4 * BT_M * SSTB) // 106496

__global__ void __launch_bounds__(256) kernelB(float* __restrict__ out) {
    extern __shared__ unsigned short sh[];
    unsigned short* Ah = sh;
    unsigned short* Al = sh + 1 * BT_M * SST;
    unsigned short* Bh = sh + 2 * BT_M * SST;
    unsigned short* Bl = sh + 3 * BT_M * SST;

    const int tid  = threadIdx.x;
    const int lane = tid & 31;
    const int wid  = tid >> 5;
    const int wr   = wid & 3;     // token group (32 rows)
    const int wc   = wid >> 2;    // d group (64 cols)
    const int tok0 = blockIdx.x * BT_M;
    const int d0   = blockIdx.y * BT_N;
    const int h    = blockIdx.z;

    // ---- stage 4 tiles: each 128 rows x 96 bf16 (rows padded to 104) ----
    const char* grh = (const char*)g_rhi;
    const char* grl = (const char*)g_rlo;
    const char* gbh = (const char*)g_bhi;
    const char* gbl = (const char*)g_blo;
    #pragma unroll
    for (int i = tid; i < BT_M * 12; i += 256) {
        int r = i / 12, q = i - r * 12;
        size_t asrc = (size_t)(tok0 + r) * 192 + q * 16;
        size_t bsrc = (size_t)(h * DOUTD + d0 + r) * 192 + q * 16;
        *(uint4*)((char*)Ah + r * SSTB + q * 16) = *(const uint4*)(grh + asrc);
        *(uint4*)((char*)Al + r * SSTB + q * 16) = *(const uint4*)(grl + asrc);
        *(uint4*)((char*)Bh + r * SSTB + q * 16) = *(const uint4*)(gbh + bsrc);
        *(uint4*)((char*)Bl + r * SSTB + q * 16) = *(const uint4*)(gbl + bsrc);
    }
    __syncthreads();

    // ldmatrix per-lane address components
    const uint32_t a_row = (lane & 15);
    const uint32_t a_k16 = (lane >> 4) & 1;                   // 0/1 -> +16B (k+8)
    const uint32_t b_row = (lane & 7) + ((lane & 16) ? 8 : 0);
    const uint32_t b_k16 = (lane & 8) ? 16 : 0;

    const uint32_t aH0 = smem_u32(Ah) + (wr * 32 + a_row) * SSTB + a_k16 * 16;
    const uint32_t aL0 = smem_u32(Al) + (wr * 32 + a_row) * SSTB + a_k16 * 16;
    const uint32_t bH0 = smem_u32(Bh) + (wc * 64 + b_row) * SSTB + b_k16;
    const uint32_t bL0 = smem_u32(Bl) + (wc * 64 + b_row) * SSTB + b_k16;

    float acc[2][8][4];
    #pragma unroll
    for (int m = 0; m < 2; m++)
        #pragma unroll
        for (int n = 0; n < 8; n++)
            #pragma unroll
            for (int e = 0; e < 4; e++) acc[m][n][e] = 0.f;

    #pragma unroll
    for (int ks = 0; ks < 6; ks++) {
        uint32_t bh[4][4], bl[4][4];
        #pragma unroll
        for (int g = 0; g < 4; g++) {
            LDSM4(bh[g], bH0 + g * 16 * SSTB + ks * 32);
            LDSM4(bl[g], bL0 + g * 16 * SSTB + ks * 32);
        }
        #pragma unroll
        for (int mt = 0; mt < 2; mt++) {
            uint32_t ah[4], al[4];
            LDSM4(ah, aH0 + mt * 16 * SSTB + ks * 32);
            LDSM4(al, aL0 + mt * 16 * SSTB + ks * 32);
            #pragma unroll
            for (int g = 0; g < 4; g++) {
                MMA16816(acc[mt][2 * g],     ah, bh[g][0], bh[g][1]);
                MMA16816(acc[mt][2 * g + 1], ah, bh[g][2], bh[g][3]);
                MMA16816(acc[mt][2 * g],     ah, bl[g][0], bl[g][1]);
                MMA16816(acc[mt][2 * g + 1], ah, bl[g][2], bl[g][3]);
                MMA16816(acc[mt][2 * g],     al, bh[g][0], bh[g][1]);
                MMA16816(acc[mt][2 * g + 1], al, bh[g][2], bh[g][3]);
            }
        }
    }

    // ---- epilogue: C frag -> gmem ----
    const int trow = lane >> 2;
    const int tcol = (lane & 3) * 2;
    #pragma unroll
    for (int mt = 0; mt < 2; mt++) {
        int tokb = tok0 + wr * 32 + mt * 16 + trow;
        float* ob0 = out + ((size_t)h * NTOK + tokb) * DOUTD + d0 + wc * 64 + tcol;
        float* ob1 = ob0 + 8 * DOUTD;
        #pragma unroll
        for (int nt = 0; nt < 8; nt++) {
            *(float2*)(ob0 + nt * 8) = make_float2(acc[mt][nt][0], acc[mt][nt][1]);
            *(float2*)(ob1 + nt * 8) = make_float2(acc[mt][nt][2], acc[mt][nt][3]);
        }
    }
}

// ---------------------------------------------------------------------------
extern "C" void kernel_launch(void* const* d_in, const int* in_sizes, int n_in,
                              void* d_out, int out_size) {
    const float* x    = (const float*)d_in[0];
    const float* dw   = (const float*)d_in[1];
    const float* db   = (const float*)d_in[2];
    const float* ntl  = (const float*)d_in[3];
    const float* gw   = (const float*)d_in[4];
    const float* gb   = (const float*)d_in[5];
    const float* lo   = (const float*)d_in[6];
    const int*   pidx = (const int*)d_in[7];
    const float* pdir = (const float*)d_in[8];
    float* out = (float*)d_out;

    const int smemA = (NOUT * A_WS + A_TOK * A_KT) * sizeof(float);   // 83456
    cudaFuncSetAttribute(kernelA, cudaFuncAttributeMaxDynamicSharedMemorySize, smemA);
    cudaFuncSetAttribute(kernelB, cudaFuncAttributeMaxDynamicSharedMemorySize, SMEM_B_BYTES);

    kernelP<<<NHEADS * NOUT, 256>>>(lo);
    kernelA<<<NTOK / A_TOK, 256, smemA>>>(x, dw, db, ntl, gw, gb, pidx, pdir);

    dim3 gridB(NTOK / BT_M, DOUTD / BT_N, NHEADS);
    kernelB<<<gridB, 256, SMEM_B_BYTES>>>(out);
}

// round 4
// speedup vs baseline: 1.3572x; 1.1696x over previous
#include <cuda_runtime.h>
#include <cuda_bf16.h>
#include <math.h>
#include <stdint.h>

// Problem constants
#define NTOK   8192
#define DIN    1024
#define NT     12
#define NI     7
#define NL     8
#define NDEC   84
#define NOUT   96
#define DOUTD  1024
#define NHEADS 3

// ---------------- scratch (device globals) ----------------
__device__ __align__(16) unsigned short g_rhi[NTOK * NOUT];           // routed hi bf16 [tok][96]
__device__ __align__(16) unsigned short g_rlo[NTOK * NOUT];           // routed lo
__device__ __align__(16) unsigned short g_bhi[NHEADS * NOUT * DOUTD]; // LO hi  [h][l][d] (native layout)
__device__ __align__(16) unsigned short g_blo[NHEADS * NOUT * DOUTD]; // LO lo
__device__ __align__(16) unsigned short g_whi[NOUT * DIN];            // W hi   [96][1024]
__device__ __align__(16) unsigned short g_wlo[NOUT * DIN];            // W lo

__device__ __forceinline__ uint32_t smem_u32(const void* p) {
    uint32_t a;
    asm("{ .reg .u64 t; cvta.to.shared.u64 t, %1; cvt.u32.u64 %0, t; }" : "=r"(a) : "l"(p));
    return a;
}
__device__ __forceinline__ void split_bf16(float x, unsigned short &h, unsigned short &l) {
    __nv_bfloat16 hb = __float2bfloat16(x);
    float hf = __bfloat162float(hb);
    __nv_bfloat16 lb = __float2bfloat16(x - hf);
    h = __bfloat16_as_ushort(hb);
    l = __bfloat16_as_ushort(lb);
}

// ---------------- mma.sync / ldmatrix ----------------
#define LDSM4(r, addr) \
    asm volatile("ldmatrix.sync.aligned.m8n8.x4.shared.b16 {%0,%1,%2,%3}, [%4];" \
        : "=r"((r)[0]), "=r"((r)[1]), "=r"((r)[2]), "=r"((r)[3]) : "r"(addr))

#define LDSM4T(r, addr) \
    asm volatile("ldmatrix.sync.aligned.m8n8.x4.trans.shared.b16 {%0,%1,%2,%3}, [%4];" \
        : "=r"((r)[0]), "=r"((r)[1]), "=r"((r)[2]), "=r"((r)[3]) : "r"(addr))

#define MMA16816(c, a, b0, b1) \
    asm volatile("mma.sync.aligned.m16n8k16.row.col.f32.bf16.bf16.f32 " \
        "{%0,%1,%2,%3}, {%4,%5,%6,%7}, {%8,%9}, {%0,%1,%2,%3};" \
        : "+f"((c)[0]), "+f"((c)[1]), "+f"((c)[2]), "+f"((c)[3]) \
        : "r"((a)[0]), "r"((a)[1]), "r"((a)[2]), "r"((a)[3]), "r"(b0), "r"(b1))

// ---------------------------------------------------------------------------
// Kernel PW: convert LO [h][l][d] and W [96][1024] to bf16 hi/lo (coalesced)
// ---------------------------------------------------------------------------
__global__ void __launch_bounds__(256) kernelPW(
    const float* __restrict__ lo, const float* __restrict__ dw, const float* __restrict__ gw)
{
    int bid = blockIdx.x;
    if (bid < 288) {
        int idx = bid * 256 + threadIdx.x;                 // < 73728 float4s
        float4 v = ((const float4*)lo)[idx];
        ushort4 hv, lv;
        split_bf16(v.x, hv.x, lv.x); split_bf16(v.y, hv.y, lv.y);
        split_bf16(v.z, hv.z, lv.z); split_bf16(v.w, hv.w, lv.w);
        *(ushort4*)(g_bhi + (size_t)idx * 4) = hv;
        *(ushort4*)(g_blo + (size_t)idx * 4) = lv;
    } else {
        int widx = (bid - 288) * 256 + threadIdx.x;        // < 24576
        int o  = widx >> 8;
        int kq = widx & 255;
        const float* src = (o < NDEC) ? (dw + (size_t)o * DIN) : (gw + (size_t)(o - NDEC) * DIN);
        float4 v = *(const float4*)(src + kq * 4);
        ushort4 hv, lv;
        split_bf16(v.x, hv.x, lv.x); split_bf16(v.y, hv.y, lv.y);
        split_bf16(v.z, hv.z, lv.z); split_bf16(v.w, hv.w, lv.w);
        *(ushort4*)(g_whi + (size_t)o * DIN + kq * 4) = hv;
        *(ushort4*)(g_wlo + (size_t)o * DIN + kq * 4) = lv;
    }
}

// ---------------------------------------------------------------------------
// Kernel A (HMMA): decisions[64 tok][96] = x[64,1024] @ W^T[1024,96]
//   bf16 hi/lo 3-term split, fp32 accum; x split in-kernel during staging.
//   Fused epilogue: sigmoid / leaf products / gate softmax -> g_rhi/g_rlo
// ---------------------------------------------------------------------------
#define AM    64
#define AKC   128
#define AST   136               // smem row stride in shorts (128 + 8)
#define ASTB  272               // bytes
#define A_AH  0
#define A_AL  (AM * AST)        // 8704 shorts
#define A_BH  (2 * AM * AST)    // 17408
#define A_BL  (2 * AM * AST + NOUT * AST)  // 30464
#define SMEM_A_BYTES ((2 * AM * AST + 2 * NOUT * AST) * 2)  // 87040
#define DEC_S 97

__global__ void __launch_bounds__(256, 1) kernelA(
    const float* __restrict__ x,
    const float* __restrict__ db,
    const float* __restrict__ ntl,
    const float* __restrict__ gb,
    const int*   __restrict__ pidx,
    const float* __restrict__ pdir)
{
    extern __shared__ unsigned short sa[];
    unsigned short* Ah = sa + A_AH;
    unsigned short* Al = sa + A_AL;
    unsigned short* Bh = sa + A_BH;
    unsigned short* Bl = sa + A_BL;
    __shared__ float s_invt[NDEC];
    __shared__ float s_bias[NDEC];
    __shared__ float s_gb[NT];
    __shared__ int   s_pi[NL * 3];
    __shared__ float s_pd[NL * 3];

    const int tid  = threadIdx.x;
    const int lane = tid & 31;
    const int wid  = tid >> 5;
    const int wr   = wid & 3;     // token group of 16
    const int wc   = wid >> 2;    // out group of 48 (0/1)
    const int tok0 = blockIdx.x * AM;

    if (tid < NDEC) {
        float t  = ntl[tid] + 0.5413f;
        float sp = (t > 20.f) ? t : log1pf(__expf(t));
        s_invt[tid] = 1.0f / sp;
        s_bias[tid] = db[tid];
    } else if (tid < NDEC + NT) {
        s_gb[tid - NDEC] = gb[tid - NDEC];
    } else if (tid < NDEC + NT + NL * 3) {
        int i = tid - NDEC - NT;
        s_pi[i] = pidx[i];
        s_pd[i] = pdir[i];
    }

    float acc[6][4];
    #pragma unroll
    for (int n = 0; n < 6; n++)
        #pragma unroll
        for (int e = 0; e < 4; e++) acc[n][e] = 0.f;

    const uint32_t aH0 = smem_u32(Ah) + (wr * 16 + (lane & 15)) * ASTB + ((lane >> 4) & 1) * 16;
    const uint32_t aL0 = aH0 + AM * ASTB;
    const uint32_t bRow = wc * 48 + (lane & 7) + ((lane & 16) ? 8 : 0);
    const uint32_t bH0 = smem_u32(Bh) + bRow * ASTB + ((lane & 8) ? 16 : 0);
    const uint32_t bL0 = bH0 + NOUT * ASTB;

    for (int kc = 0; kc < 8; kc++) {
        const int k0 = kc * AKC;
        __syncthreads();
        // stage x chunk [64][128] fp32 -> split bf16 hi/lo
        #pragma unroll
        for (int it = 0; it < 8; it++) {
            int idx = it * 256 + tid;            // < 2048 float4
            int r = idx >> 5, kq = idx & 31;
            float4 v = *(const float4*)(x + (size_t)(tok0 + r) * DIN + k0 + kq * 4);
            ushort4 hv, lv;
            split_bf16(v.x, hv.x, lv.x); split_bf16(v.y, hv.y, lv.y);
            split_bf16(v.z, hv.z, lv.z); split_bf16(v.w, hv.w, lv.w);
            *(ushort4*)(Ah + r * AST + kq * 4) = hv;
            *(ushort4*)(Al + r * AST + kq * 4) = lv;
        }
        // stage W chunk [96][128] bf16 hi/lo
        #pragma unroll
        for (int it = 0; it < 6; it++) {
            int idx = it * 256 + tid;            // < 1536 uint4
            int r = idx >> 4, q = idx & 15;
            *(uint4*)(Bh + r * AST + q * 8) = *(const uint4*)(g_whi + (size_t)r * DIN + k0 + q * 8);
            *(uint4*)(Bl + r * AST + q * 8) = *(const uint4*)(g_wlo + (size_t)r * DIN + k0 + q * 8);
        }
        __syncthreads();

        #pragma unroll
        for (int ks = 0; ks < 8; ks++) {
            uint32_t ah[4], al[4];
            LDSM4(ah, aH0 + ks * 32);
            LDSM4(al, aL0 + ks * 32);
            #pragma unroll
            for (int g = 0; g < 3; g++) {
                uint32_t bh[4], bl[4];
                LDSM4(bh, bH0 + g * 16 * ASTB + ks * 32);
                LDSM4(bl, bL0 + g * 16 * ASTB + ks * 32);
                MMA16816(acc[2 * g],     ah, bh[0], bh[1]);
                MMA16816(acc[2 * g + 1], ah, bh[2], bh[3]);
                MMA16816(acc[2 * g],     ah, bl[0], bl[1]);
                MMA16816(acc[2 * g + 1], ah, bl[2], bl[3]);
                MMA16816(acc[2 * g],     al, bh[0], bh[1]);
                MMA16816(acc[2 * g + 1], al, bh[2], bh[3]);
            }
        }
    }

    __syncthreads();
    float* Dec = (float*)sa;   // [64][97]
    const int trow = lane >> 2;
    const int tcol = (lane & 3) * 2;
    #pragma unroll
    for (int nt = 0; nt < 6; nt++) {
        int col = wc * 48 + nt * 8 + tcol;
        Dec[(wr * 16 + trow) * DEC_S + col]     = acc[nt][0];
        Dec[(wr * 16 + trow) * DEC_S + col + 1] = acc[nt][1];
        Dec[(wr * 16 + trow + 8) * DEC_S + col]     = acc[nt][2];
        Dec[(wr * 16 + trow + 8) * DEC_S + col + 1] = acc[nt][3];
    }
    __syncthreads();

    if (tid < AM) {
        const int token = tok0 + tid;
        const float* d = Dec + tid * DEC_S;

        float g[NT];
        float m = -1e30f;
        #pragma unroll
        for (int t = 0; t < NT; t++) { g[t] = d[NDEC + t] + s_gb[t]; m = fmaxf(m, g[t]); }
        float sum = 0.f;
        #pragma unroll
        for (int t = 0; t < NT; t++) { g[t] = __expf(g[t] - m); sum += g[t]; }
        const float inv = 1.0f / sum;

        unsigned short* rh = g_rhi + (size_t)token * NOUT;
        unsigned short* rl = g_rlo + (size_t)token * NOUT;

        #pragma unroll
        for (int t = 0; t < NT; t++) {
            const float wgt = g[t] * inv;
            float sg[NI];
            #pragma unroll
            for (int n = 0; n < NI; n++) {
                float z = (d[t * NI + n] + s_bias[t * NI + n]) * s_invt[t * NI + n];
                sg[n] = 1.0f / (1.0f + __expf(-z));
            }
            #pragma unroll
            for (int l = 0; l < NL; l++) {
                float p = wgt;
                #pragma unroll
                for (int dd = 0; dd < 3; dd++) {
                    float sv  = sg[s_pi[l * 3 + dd]];
                    float dir = s_pd[l * 3 + dd];
                    p *= dir * sv + (1.f - dir) * (1.f - sv);
                }
                unsigned short hs, ls;
                split_bf16(p, hs, ls);
                rh[t * NL + l] = hs;
                rl[t * NL + l] = ls;
            }
        }
    }
}

// ---------------------------------------------------------------------------
// Kernel B (HMMA): out[h, 128 tok, 128 d] = routed[128,96] @ LO[96,128]
//   A: routed [tok][l] row-major (non-trans ldmatrix)
//   B: LO [l][d] row-major, loaded with ldmatrix.trans (col frags)
// ---------------------------------------------------------------------------
#define BT_M  128
#define BT_N  128
#define SSTA  104                 // A row stride shorts (96+8)
#define SSTAB 208
#define SSTB  136                 // B row stride shorts (128+8)
#define SSTBB 272
#define B_AH  0
#define B_AL  (BT_M * SSTA)                    // 13312
#define B_BH  (2 * BT_M * SSTA)                // 26624
#define B_BL  (2 * BT_M * SSTA + NOUT * SSTB)  // 39680
#define SMEM_B_BYTES ((2 * BT_M * SSTA + 2 * NOUT * SSTB) * 2)  // 105472

__global__ void __launch_bounds__(256) kernelB(float* __restrict__ out) {
    extern __shared__ unsigned short sh[];
    unsigned short* Ah = sh + B_AH;
    unsigned short* Al = sh + B_AL;
    unsigned short* Bh = sh + B_BH;
    unsigned short* Bl = sh + B_BL;

    const int tid  = threadIdx.x;
    const int lane = tid & 31;
    const int wid  = tid >> 5;
    const int wr   = wid & 3;     // token group (32 rows)
    const int wc   = wid >> 2;    // d group (64 cols)
    const int tok0 = blockIdx.x * BT_M;
    const int d0   = blockIdx.y * BT_N;
    const int h    = blockIdx.z;

    // stage A: routed 128 tok x 96 l (hi+lo)
    #pragma unroll
    for (int i = tid; i < BT_M * 12; i += 256) {
        int r = i / 12, q = i - r * 12;
        size_t src = (size_t)(tok0 + r) * 192 + q * 16;   // bytes
        *(uint4*)((char*)Ah + r * SSTAB + q * 16) = *(const uint4*)((const char*)g_rhi + src);
        *(uint4*)((char*)Al + r * SSTAB + q * 16) = *(const uint4*)((const char*)g_rlo + src);
    }
    // stage B: LO 96 l x 128 d (hi+lo), native [h][l][d] layout
    #pragma unroll
    for (int i = tid; i < NOUT * 16; i += 256) {
        int r = i >> 4, q = i & 15;
        size_t src = ((size_t)(h * NOUT + r) * DOUTD + d0 + q * 8);  // shorts
        *(uint4*)(Bh + r * SSTB + q * 8) = *(const uint4*)(g_bhi + src);
        *(uint4*)(Bl + r * SSTB + q * 8) = *(const uint4*)(g_blo + src);
    }
    __syncthreads();

    // A (row-major m16k16)
    const uint32_t aH0 = smem_u32(Ah) + (wr * 32 + (lane & 15)) * SSTAB + ((lane >> 4) & 1) * 16;
    const uint32_t aL0 = aH0 + BT_M * SSTAB;
    // B (trans: rows = k(l), cols = n(d))
    const uint32_t bH0 = smem_u32(Bh) + (lane & 15) * SSTBB + (wc * 64 + ((lane >> 4) & 1) * 8) * 2;
    const uint32_t bL0 = bH0 + NOUT * SSTBB;

    float acc[2][8][4];
    #pragma unroll
    for (int m = 0; m < 2; m++)
        #pragma unroll
        for (int n = 0; n < 8; n++)
            #pragma unroll
            for (int e = 0; e < 4; e++) acc[m][n][e] = 0.f;

    #pragma unroll
    for (int ks = 0; ks < 6; ks++) {
        uint32_t bh[4][4], bl[4][4];
        #pragma unroll
        for (int g = 0; g < 4; g++) {
            LDSM4T(bh[g], bH0 + g * 32 + ks * 16 * SSTBB);
            LDSM4T(bl[g], bL0 + g * 32 + ks * 16 * SSTBB);
        }
        #pragma unroll
        for (int mt = 0; mt < 2; mt++) {
            uint32_t ah[4], al[4];
            LDSM4(ah, aH0 + mt * 16 * SSTAB + ks * 32);
            LDSM4(al, aL0 + mt * 16 * SSTAB + ks * 32);
            #pragma unroll
            for (int g = 0; g < 4; g++) {
                MMA16816(acc[mt][2 * g],     ah, bh[g][0], bh[g][1]);
                MMA16816(acc[mt][2 * g + 1], ah, bh[g][2], bh[g][3]);
                MMA16816(acc[mt][2 * g],     ah, bl[g][0], bl[g][1]);
                MMA16816(acc[mt][2 * g + 1], ah, bl[g][2], bl[g][3]);
                MMA16816(acc[mt][2 * g],     al, bh[g][0], bh[g][1]);
                MMA16816(acc[mt][2 * g + 1], al, bh[g][2], bh[g][3]);
            }
        }
    }

    const int trow = lane >> 2;
    const int tcol = (lane & 3) * 2;
    #pragma unroll
    for (int mt = 0; mt < 2; mt++) {
        int tokb = tok0 + wr * 32 + mt * 16 + trow;
        float* ob0 = out + ((size_t)h * NTOK + tokb) * DOUTD + d0 + wc * 64 + tcol;
        float* ob1 = ob0 + 8 * DOUTD;
        #pragma unroll
        for (int nt = 0; nt < 8; nt++) {
            *(float2*)(ob0 + nt * 8) = make_float2(acc[mt][nt][0], acc[mt][nt][1]);
            *(float2*)(ob1 + nt * 8) = make_float2(acc[mt][nt][2], acc[mt][nt][3]);
        }
    }
}

// ---------------------------------------------------------------------------
extern "C" void kernel_launch(void* const* d_in, const int* in_sizes, int n_in,
                              void* d_out, int out_size) {
    const float* x    = (const float*)d_in[0];
    const float* dw   = (const float*)d_in[1];
    const float* db   = (const float*)d_in[2];
    const float* ntl  = (const float*)d_in[3];
    const float* gw   = (const float*)d_in[4];
    const float* gb   = (const float*)d_in[5];
    const float* lo   = (const float*)d_in[6];
    const int*   pidx = (const int*)d_in[7];
    const float* pdir = (const float*)d_in[8];
    float* out = (float*)d_out;

    cudaFuncSetAttribute(kernelA, cudaFuncAttributeMaxDynamicSharedMemorySize, SMEM_A_BYTES);
    cudaFuncSetAttribute(kernelB, cudaFuncAttributeMaxDynamicSharedMemorySize, SMEM_B_BYTES);

    kernelPW<<<384, 256>>>(lo, dw, gw);
    kernelA<<<NTOK / AM, 256, SMEM_A_BYTES>>>(x, db, ntl, gb, pidx, pdir);

    dim3 gridB(NTOK / BT_M, DOUTD / BT_N, NHEADS);
    kernelB<<<gridB, 256, SMEM_B_BYTES>>>(out);
}

// round 5
// speedup vs baseline: 1.6834x; 1.2404x over previous
#include <cuda_runtime.h>
#include <cuda_bf16.h>
#include <math.h>
#include <stdint.h>

// Problem constants
#define NTOK   8192
#define DIN    1024
#define NT     12
#define NI     7
#define NL     8
#define NDEC   84
#define NOUT   96
#define DOUTD  1024
#define NHEADS 3

// ---------------- scratch (device globals) ----------------
__device__ __align__(16) unsigned short g_rhi[NTOK * NOUT];           // routed hi bf16 [tok][96]
__device__ __align__(16) unsigned short g_rlo[NTOK * NOUT];           // routed lo
__device__ __align__(16) unsigned short g_bhi[NHEADS * NOUT * DOUTD]; // LO hi  [h][l][d]
__device__ __align__(16) unsigned short g_blo[NHEADS * NOUT * DOUTD]; // LO lo
__device__ __align__(16) unsigned short g_whi[NOUT * DIN];            // W hi   [96][1024]
__device__ __align__(16) unsigned short g_wlo[NOUT * DIN];            // W lo

__device__ __forceinline__ uint32_t smem_u32(const void* p) {
    uint32_t a;
    asm("{ .reg .u64 t; cvta.to.shared.u64 t, %1; cvt.u32.u64 %0, t; }" : "=r"(a) : "l"(p));
    return a;
}
__device__ __forceinline__ void split_bf16(float x, unsigned short &h, unsigned short &l) {
    __nv_bfloat16 hb = __float2bfloat16(x);
    float hf = __bfloat162float(hb);
    __nv_bfloat16 lb = __float2bfloat16(x - hf);
    h = __bfloat16_as_ushort(hb);
    l = __bfloat16_as_ushort(lb);
}

// ---------------- mma.sync / ldmatrix / cp.async ----------------
#define LDSM4(r, addr) \
    asm volatile("ldmatrix.sync.aligned.m8n8.x4.shared.b16 {%0,%1,%2,%3}, [%4];" \
        : "=r"((r)[0]), "=r"((r)[1]), "=r"((r)[2]), "=r"((r)[3]) : "r"(addr))

#define LDSM4T(r, addr) \
    asm volatile("ldmatrix.sync.aligned.m8n8.x4.trans.shared.b16 {%0,%1,%2,%3}, [%4];" \
        : "=r"((r)[0]), "=r"((r)[1]), "=r"((r)[2]), "=r"((r)[3]) : "r"(addr))

#define MMA16816(c, a, b0, b1) \
    asm volatile("mma.sync.aligned.m16n8k16.row.col.f32.bf16.bf16.f32 " \
        "{%0,%1,%2,%3}, {%4,%5,%6,%7}, {%8,%9}, {%0,%1,%2,%3};" \
        : "+f"((c)[0]), "+f"((c)[1]), "+f"((c)[2]), "+f"((c)[3]) \
        : "r"((a)[0]), "r"((a)[1]), "r"((a)[2]), "r"((a)[3]), "r"(b0), "r"(b1))

#define CP16(sm, gm) \
    asm volatile("cp.async.cg.shared.global [%0], [%1], 16;" :: "r"(sm), "l"(gm))
#define CP_COMMIT() asm volatile("cp.async.commit_group;" ::: "memory")
#define CP_WAIT0()  asm volatile("cp.async.wait_group 0;" ::: "memory")

// ---------------------------------------------------------------------------
// Kernel PW: convert LO [h][l][d] and W [96][1024] to bf16 hi/lo (coalesced)
// ---------------------------------------------------------------------------
__global__ void __launch_bounds__(256) kernelPW(
    const float* __restrict__ lo, const float* __restrict__ dw, const float* __restrict__ gw)
{
    int bid = blockIdx.x;
    if (bid < 288) {
        int idx = bid * 256 + threadIdx.x;
        float4 v = ((const float4*)lo)[idx];
        ushort4 hv, lv;
        split_bf16(v.x, hv.x, lv.x); split_bf16(v.y, hv.y, lv.y);
        split_bf16(v.z, hv.z, lv.z); split_bf16(v.w, hv.w, lv.w);
        *(ushort4*)(g_bhi + (size_t)idx * 4) = hv;
        *(ushort4*)(g_blo + (size_t)idx * 4) = lv;
    } else {
        int widx = (bid - 288) * 256 + threadIdx.x;
        int o  = widx >> 8;
        int kq = widx & 255;
        const float* src = (o < NDEC) ? (dw + (size_t)o * DIN) : (gw + (size_t)(o - NDEC) * DIN);
        float4 v = *(const float4*)(src + kq * 4);
        ushort4 hv, lv;
        split_bf16(v.x, hv.x, lv.x); split_bf16(v.y, hv.y, lv.y);
        split_bf16(v.z, hv.z, lv.z); split_bf16(v.w, hv.w, lv.w);
        *(ushort4*)(g_whi + (size_t)o * DIN + kq * 4) = hv;
        *(ushort4*)(g_wlo + (size_t)o * DIN + kq * 4) = lv;
    }
}

// ---------------------------------------------------------------------------
// Kernel A (HMMA, double-buffered): decisions[64,96] = x[64,1024] @ W^T
//   x LDG-prefetched + split in-kernel; W via cp.async one chunk ahead.
// ---------------------------------------------------------------------------
#define AM    64
#define AKC   128
#define AST   136                 // shorts per row (128+8)
#define ASTB  272
#define A_AH  0
#define A_AL  (AM * AST)                    // 8704
#define A_BH  (2 * AM * AST)                // 17408
#define A_BL  (2 * AM * AST + NOUT * AST)   // 30464
#define BUF_SHORTS (2 * AM * AST + 2 * NOUT * AST)   // 43520
#define BUF_BYTES  (BUF_SHORTS * 2)                  // 87040
#define SMEM_A_BYTES (2 * BUF_BYTES)                 // 174080
#define DEC_S 97

__global__ void __launch_bounds__(256, 1) kernelA(
    const float* __restrict__ x,
    const float* __restrict__ db,
    const float* __restrict__ ntl,
    const float* __restrict__ gb,
    const int*   __restrict__ pidx,
    const float* __restrict__ pdir)
{
    extern __shared__ __align__(16) unsigned short sa[];
    __shared__ float s_invt[NDEC];
    __shared__ float s_bias[NDEC];
    __shared__ float s_gb[NT];
    __shared__ int   s_pi[NL * 3];
    __shared__ float s_pd[NL * 3];

    const int tid  = threadIdx.x;
    const int lane = tid & 31;
    const int wid  = tid >> 5;
    const int wr   = wid & 3;
    const int wc   = wid >> 2;
    const int tok0 = blockIdx.x * AM;
    const uint32_t smbase = smem_u32(sa);

    if (tid < NDEC) {
        float t  = ntl[tid] + 0.5413f;
        float sp = (t > 20.f) ? t : log1pf(__expf(t));
        s_invt[tid] = 1.0f / sp;
        s_bias[tid] = db[tid];
    } else if (tid < NDEC + NT) {
        s_gb[tid - NDEC] = gb[tid - NDEC];
    } else if (tid < NDEC + NT + NL * 3) {
        int i = tid - NDEC - NT;
        s_pi[i] = pidx[i];
        s_pd[i] = pdir[i];
    }

    // staging index precompute
    const int xr  = tid >> 5;           // base row for x loads (it*8 rows apart? no: idx layout)
    // x: idx = it*256+tid; r=idx>>5 = it*8 + (tid>>5); kq = tid&31
    const int xkq = tid & 31;
    // W: idx = it*256+tid; r = idx>>4 = it*16 + (tid>>4); q = tid&15
    const int wrr = tid >> 4;
    const int wq  = tid & 15;

    float acc[6][4];
    #pragma unroll
    for (int n = 0; n < 6; n++)
        #pragma unroll
        for (int e = 0; e < 4; e++) acc[n][e] = 0.f;

    const uint32_t aoff = (wr * 16 + (lane & 15)) * ASTB + ((lane >> 4) & 1) * 16;
    const uint32_t boff = (wc * 48 + (lane & 7) + ((lane & 16) ? 8 : 0)) * ASTB + ((lane & 8) ? 16 : 0);

    // ---- prologue: LDG x chunk 0, cp.async W chunk 0 -> buf 0 ----
    float4 xv[8];
    #pragma unroll
    for (int it = 0; it < 8; it++) {
        int r = it * 8 + xr;
        xv[it] = *(const float4*)(x + (size_t)(tok0 + r) * DIN + xkq * 4);
    }
    #pragma unroll
    for (int it = 0; it < 6; it++) {
        int r = it * 16 + wrr;
        uint32_t dsth = smbase + (A_BH + r * AST + wq * 8) * 2;
        CP16(dsth, g_whi + (size_t)r * DIN + wq * 8);
        CP16(dsth + (NOUT * AST) * 2, g_wlo + (size_t)r * DIN + wq * 8);
    }
    CP_COMMIT();

    for (int kc = 0; kc < 8; kc++) {
        const int b = kc & 1;
        unsigned short* Ah = sa + b * BUF_SHORTS;
        unsigned short* Al = Ah + A_AL;
        const uint32_t sb = smbase + b * BUF_BYTES;

        // prefetch next x chunk into regs (latency overlapped with MMA below)
        float4 xn[8];
        if (kc < 7) {
            #pragma unroll
            for (int it = 0; it < 8; it++) {
                int r = it * 8 + xr;
                xn[it] = *(const float4*)(x + (size_t)(tok0 + r) * DIN + (kc + 1) * AKC + xkq * 4);
            }
        }

        // cvt + STS current x chunk
        #pragma unroll
        for (int it = 0; it < 8; it++) {
            int r = it * 8 + xr;
            ushort4 hv, lv;
            split_bf16(xv[it].x, hv.x, lv.x); split_bf16(xv[it].y, hv.y, lv.y);
            split_bf16(xv[it].z, hv.z, lv.z); split_bf16(xv[it].w, hv.w, lv.w);
            *(ushort4*)(Ah + r * AST + xkq * 4) = hv;
            *(ushort4*)(Al + r * AST + xkq * 4) = lv;
        }
        CP_WAIT0();
        __syncthreads();

        // issue next W chunk into other buffer (flies during MMA)
        if (kc < 7) {
            const uint32_t so = smbase + (1 - b) * BUF_BYTES;
            #pragma unroll
            for (int it = 0; it < 6; it++) {
                int r = it * 16 + wrr;
                uint32_t dsth = so + (A_BH + r * AST + wq * 8) * 2;
                CP16(dsth, g_whi + (size_t)r * DIN + (kc + 1) * AKC + wq * 8);
                CP16(dsth + (NOUT * AST) * 2, g_wlo + (size_t)r * DIN + (kc + 1) * AKC + wq * 8);
            }
            CP_COMMIT();
        }

        // MMA on buffer b
        const uint32_t aH0 = sb + aoff;
        const uint32_t aL0 = aH0 + AM * ASTB;
        const uint32_t bH0 = sb + A_BH * 2 + boff;
        const uint32_t bL0 = bH0 + NOUT * ASTB;
        #pragma unroll
        for (int ks = 0; ks < 8; ks++) {
            uint32_t ah[4], al[4];
            LDSM4(ah, aH0 + ks * 32);
            LDSM4(al, aL0 + ks * 32);
            #pragma unroll
            for (int g = 0; g < 3; g++) {
                uint32_t bh[4], bl[4];
                LDSM4(bh, bH0 + g * 16 * ASTB + ks * 32);
                LDSM4(bl, bL0 + g * 16 * ASTB + ks * 32);
                MMA16816(acc[2 * g],     ah, bh[0], bh[1]);
                MMA16816(acc[2 * g + 1], ah, bh[2], bh[3]);
                MMA16816(acc[2 * g],     ah, bl[0], bl[1]);
                MMA16816(acc[2 * g + 1], ah, bl[2], bl[3]);
                MMA16816(acc[2 * g],     al, bh[0], bh[1]);
                MMA16816(acc[2 * g + 1], al, bh[2], bh[3]);
            }
        }
        __syncthreads();

        if (kc < 7) {
            #pragma unroll
            for (int it = 0; it < 8; it++) xv[it] = xn[it];
        }
    }

    // ---- epilogue ----
    float* Dec = (float*)sa;   // [64][97]
    const int trow = lane >> 2;
    const int tcol = (lane & 3) * 2;
    #pragma unroll
    for (int nt = 0; nt < 6; nt++) {
        int col = wc * 48 + nt * 8 + tcol;
        Dec[(wr * 16 + trow) * DEC_S + col]         = acc[nt][0];
        Dec[(wr * 16 + trow) * DEC_S + col + 1]     = acc[nt][1];
        Dec[(wr * 16 + trow + 8) * DEC_S + col]     = acc[nt][2];
        Dec[(wr * 16 + trow + 8) * DEC_S + col + 1] = acc[nt][3];
    }
    __syncthreads();

    if (tid < AM) {
        const int token = tok0 + tid;
        const float* d = Dec + tid * DEC_S;

        float g[NT];
        float m = -1e30f;
        #pragma unroll
        for (int t = 0; t < NT; t++) { g[t] = d[NDEC + t] + s_gb[t]; m = fmaxf(m, g[t]); }
        float sum = 0.f;
        #pragma unroll
        for (int t = 0; t < NT; t++) { g[t] = __expf(g[t] - m); sum += g[t]; }
        const float inv = 1.0f / sum;

        unsigned short* rh = g_rhi + (size_t)token * NOUT;
        unsigned short* rl = g_rlo + (size_t)token * NOUT;

        #pragma unroll
        for (int t = 0; t < NT; t++) {
            const float wgt = g[t] * inv;
            float sg[NI];
            #pragma unroll
            for (int n = 0; n < NI; n++) {
                float z = (d[t * NI + n] + s_bias[t * NI + n]) * s_invt[t * NI + n];
                sg[n] = 1.0f / (1.0f + __expf(-z));
            }
            #pragma unroll
            for (int l = 0; l < NL; l++) {
                float p = wgt;
                #pragma unroll
                for (int dd = 0; dd < 3; dd++) {
                    float sv  = sg[s_pi[l * 3 + dd]];
                    float dir = s_pd[l * 3 + dd];
                    p *= dir * sv + (1.f - dir) * (1.f - sv);
                }
                unsigned short hs, ls;
                split_bf16(p, hs, ls);
                rh[t * NL + l] = hs;
                rl[t * NL + l] = ls;
            }
        }
    }
}

// ---------------------------------------------------------------------------
// Kernel B (HMMA): out[h, 128 tok, 256 d] = routed[128,96] @ LO[96,256]
//   512 threads, 16 warps (4 tok-groups x 4 d-groups), cp.async staging
// ---------------------------------------------------------------------------
#define BT_M  128
#define BT_N  256
#define SSTA  104                 // A row stride shorts (96+8)
#define SSTAB 208
#define SSTB  264                 // B row stride shorts (256+8)
#define SSTBB 528
#define B_AH  0
#define B_AL  (BT_M * SSTA)                    // 13312
#define B_BH  (2 * BT_M * SSTA)                // 26624
#define B_BL  (2 * BT_M * SSTA + NOUT * SSTB)  // 51968
#define SMEM_B_BYTES ((2 * BT_M * SSTA + 2 * NOUT * SSTB) * 2)  // 154624

__global__ void __launch_bounds__(512, 1) kernelB(float* __restrict__ out) {
    extern __shared__ __align__(16) unsigned short sh[];

    const int tid  = threadIdx.x;
    const int lane = tid & 31;
    const int wid  = tid >> 5;
    const int wr   = wid & 3;     // token group (32 rows)
    const int wc   = wid >> 2;    // d group (64 cols)
    const int tok0 = blockIdx.x * BT_M;
    const int d0   = blockIdx.y * BT_N;
    const int h    = blockIdx.z;
    const uint32_t smbase = smem_u32(sh);

    // stage A: routed 128 tok x 96 l (hi+lo) -- 1536 uint4 each
    {
        int r = tid / 4, q = tid & 3;           // 128 rows x (4 of 12 q per pass)
        #pragma unroll
        for (int p = 0; p < 3; p++) {
            int qq = p * 4 + q;
            size_t src = (size_t)(tok0 + r) * 192 + qq * 16;   // bytes
            uint32_t dst = smbase + (B_AH + r * SSTA) * 2 + qq * 16;
            CP16(dst, (const char*)g_rhi + src);
            CP16(dst + BT_M * SSTAB, (const char*)g_rlo + src);
        }
    }
    // stage B: LO 96 l x 256 d (hi+lo) -- 3072 uint4 each
    {
        int r = tid / 16, q = tid & 15;         // 32 rows per pass x 16 q
        #pragma unroll
        for (int p = 0; p < 3; p++) {
            int rr = p * 32 + r;
            size_t src = ((size_t)(h * NOUT + rr) * DOUTD + d0 + q * 16) * 2;  // bytes
            uint32_t dst = smbase + (B_BH + rr * SSTB) * 2 + q * 32;
            CP16(dst,      (const char*)g_bhi + src);
            CP16(dst + 16, (const char*)g_bhi + src + 16);
            CP16(dst + NOUT * SSTBB,      (const char*)g_blo + src);
            CP16(dst + NOUT * SSTBB + 16, (const char*)g_blo + src + 16);
        }
    }
    CP_COMMIT();
    CP_WAIT0();
    __syncthreads();

    const uint32_t aH0 = smbase + ((wr * 32 + (lane & 15)) * SSTAB) + ((lane >> 4) & 1) * 16;
    const uint32_t aL0 = aH0 + BT_M * SSTAB;
    const uint32_t bH0 = smbase + B_BH * 2 + (lane & 15) * SSTBB + (wc * 64 + ((lane >> 4) & 1) * 8) * 2;
    const uint32_t bL0 = bH0 + NOUT * SSTBB;

    float acc[2][8][4];
    #pragma unroll
    for (int m = 0; m < 2; m++)
        #pragma unroll
        for (int n = 0; n < 8; n++)
            #pragma unroll
            for (int e = 0; e < 4; e++) acc[m][n][e] = 0.f;

    #pragma unroll
    for (int ks = 0; ks < 6; ks++) {
        uint32_t ah[2][4], al[2][4];
        #pragma unroll
        for (int mt = 0; mt < 2; mt++) {
            LDSM4(ah[mt], aH0 + mt * 16 * SSTAB + ks * 32);
            LDSM4(al[mt], aL0 + mt * 16 * SSTAB + ks * 32);
        }
        #pragma unroll
        for (int g = 0; g < 4; g++) {
            uint32_t bh[4], bl[4];
            LDSM4T(bh, bH0 + g * 32 + ks * 16 * SSTBB);
            LDSM4T(bl, bL0 + g * 32 + ks * 16 * SSTBB);
            #pragma unroll
            for (int mt = 0; mt < 2; mt++) {
                MMA16816(acc[mt][2 * g],     ah[mt], bh[0], bh[1]);
                MMA16816(acc[mt][2 * g + 1], ah[mt], bh[2], bh[3]);
                MMA16816(acc[mt][2 * g],     ah[mt], bl[0], bl[1]);
                MMA16816(acc[mt][2 * g + 1], ah[mt], bl[2], bl[3]);
                MMA16816(acc[mt][2 * g],     al[mt], bh[0], bh[1]);
                MMA16816(acc[mt][2 * g + 1], al[mt], bh[2], bh[3]);
            }
        }
    }

    const int trow = lane >> 2;
    const int tcol = (lane & 3) * 2;
    #pragma unroll
    for (int mt = 0; mt < 2; mt++) {
        int tokb = tok0 + wr * 32 + mt * 16 + trow;
        float* ob0 = out + ((size_t)h * NTOK + tokb) * DOUTD + d0 + wc * 64 + tcol;
        float* ob1 = ob0 + 8 * DOUTD;
        #pragma unroll
        for (int nt = 0; nt < 8; nt++) {
            *(float2*)(ob0 + nt * 8) = make_float2(acc[mt][nt][0], acc[mt][nt][1]);
            *(float2*)(ob1 + nt * 8) = make_float2(acc[mt][nt][2], acc[mt][nt][3]);
        }
    }
}

// ---------------------------------------------------------------------------
extern "C" void kernel_launch(void* const* d_in, const int* in_sizes, int n_in,
                              void* d_out, int out_size) {
    const float* x    = (const float*)d_in[0];
    const float* dw   = (const float*)d_in[1];
    const float* db   = (const float*)d_in[2];
    const float* ntl  = (const float*)d_in[3];
    const float* gw   = (const float*)d_in[4];
    const float* gb   = (const float*)d_in[5];
    const float* lo   = (const float*)d_in[6];
    const int*   pidx = (const int*)d_in[7];
    const float* pdir = (const float*)d_in[8];
    float* out = (float*)d_out;

    cudaFuncSetAttribute(kernelA, cudaFuncAttributeMaxDynamicSharedMemorySize, SMEM_A_BYTES);
    cudaFuncSetAttribute(kernelB, cudaFuncAttributeMaxDynamicSharedMemorySize, SMEM_B_BYTES);

    kernelPW<<<384, 256>>>(lo, dw, gw);
    kernelA<<<NTOK / AM, 256, SMEM_A_BYTES>>>(x, db, ntl, gb, pidx, pdir);

    dim3 gridB(NTOK / BT_M, DOUTD / BT_N, NHEADS);
    kernelB<<<gridB, 512, SMEM_B_BYTES>>>(out);
}

// round 6
// speedup vs baseline: 1.8986x; 1.1278x over previous
#include <cuda_runtime.h>
#include <cuda_bf16.h>
#include <math.h>
#include <stdint.h>

// Problem constants
#define NTOK   8192
#define DIN    1024
#define NT     12
#define NI     7
#define NL     8
#define NDEC   84
#define NOUT   96
#define DOUTD  1024
#define NHEADS 3

// ---------------- scratch (device globals) ----------------
__device__ __align__(16) unsigned short g_rhi[NTOK * NOUT];           // routed hi bf16 [tok][96]
__device__ __align__(16) unsigned short g_rlo[NTOK * NOUT];           // routed lo
__device__ __align__(16) unsigned short g_bhi[NHEADS * NOUT * DOUTD]; // LO hi  [h][l][d]
__device__ __align__(16) unsigned short g_blo[NHEADS * NOUT * DOUTD]; // LO lo
__device__ __align__(16) unsigned short g_whi[NOUT * DIN];            // W hi   [96][1024]
__device__ __align__(16) unsigned short g_wlo[NOUT * DIN];            // W lo

__device__ __forceinline__ uint32_t smem_u32(const void* p) {
    uint32_t a;
    asm("{ .reg .u64 t; cvta.to.shared.u64 t, %1; cvt.u32.u64 %0, t; }" : "=r"(a) : "l"(p));
    return a;
}
__device__ __forceinline__ void split_bf16(float x, unsigned short &h, unsigned short &l) {
    __nv_bfloat16 hb = __float2bfloat16(x);
    float hf = __bfloat162float(hb);
    __nv_bfloat16 lb = __float2bfloat16(x - hf);
    h = __bfloat16_as_ushort(hb);
    l = __bfloat16_as_ushort(lb);
}

// ---------------- mma.sync / ldmatrix / cp.async ----------------
#define LDSM4(r, addr) \
    asm volatile("ldmatrix.sync.aligned.m8n8.x4.shared.b16 {%0,%1,%2,%3}, [%4];" \
        : "=r"((r)[0]), "=r"((r)[1]), "=r"((r)[2]), "=r"((r)[3]) : "r"(addr))

#define LDSM4T(r, addr) \
    asm volatile("ldmatrix.sync.aligned.m8n8.x4.trans.shared.b16 {%0,%1,%2,%3}, [%4];" \
        : "=r"((r)[0]), "=r"((r)[1]), "=r"((r)[2]), "=r"((r)[3]) : "r"(addr))

#define MMA16816(c, a, b0, b1) \
    asm volatile("mma.sync.aligned.m16n8k16.row.col.f32.bf16.bf16.f32 " \
        "{%0,%1,%2,%3}, {%4,%5,%6,%7}, {%8,%9}, {%0,%1,%2,%3};" \
        : "+f"((c)[0]), "+f"((c)[1]), "+f"((c)[2]), "+f"((c)[3]) \
        : "r"((a)[0]), "r"((a)[1]), "r"((a)[2]), "r"((a)[3]), "r"(b0), "r"(b1))

#define CP16(sm, gm) \
    asm volatile("cp.async.cg.shared.global [%0], [%1], 16;" :: "r"(sm), "l"(gm))
#define CP_COMMIT() asm volatile("cp.async.commit_group;" ::: "memory")
#define CP_WAIT0()  asm volatile("cp.async.wait_group 0;" ::: "memory")

// ---------------------------------------------------------------------------
// Kernel W: convert W [96][1024] fp32 -> bf16 hi/lo
// ---------------------------------------------------------------------------
__global__ void __launch_bounds__(256) kernelW(
    const float* __restrict__ dw, const float* __restrict__ gw)
{
    int widx = blockIdx.x * 256 + threadIdx.x;   // < 24576
    int o  = widx >> 8;
    int kq = widx & 255;
    const float* src = (o < NDEC) ? (dw + (size_t)o * DIN) : (gw + (size_t)(o - NDEC) * DIN);
    float4 v = *(const float4*)(src + kq * 4);
    ushort4 hv, lv;
    split_bf16(v.x, hv.x, lv.x); split_bf16(v.y, hv.y, lv.y);
    split_bf16(v.z, hv.z, lv.z); split_bf16(v.w, hv.w, lv.w);
    *(ushort4*)(g_whi + (size_t)o * DIN + kq * 4) = hv;
    *(ushort4*)(g_wlo + (size_t)o * DIN + kq * 4) = lv;
}

// ---------------------------------------------------------------------------
// Kernel LO: convert leaf_outputs [h][l][d] fp32 -> bf16 hi/lo (coalesced)
// ---------------------------------------------------------------------------
__global__ void __launch_bounds__(256) kernelLO(const float* __restrict__ lo) {
    int idx = blockIdx.x * 256 + threadIdx.x;    // < 73728 float4
    float4 v = ((const float4*)lo)[idx];
    ushort4 hv, lv;
    split_bf16(v.x, hv.x, lv.x); split_bf16(v.y, hv.y, lv.y);
    split_bf16(v.z, hv.z, lv.z); split_bf16(v.w, hv.w, lv.w);
    *(ushort4*)(g_bhi + (size_t)idx * 4) = hv;
    *(ushort4*)(g_blo + (size_t)idx * 4) = lv;
}

// ---------------------------------------------------------------------------
// Kernel A (HMMA, double-buffered): decisions[64,96] = x[64,1024] @ W^T
// ---------------------------------------------------------------------------
#define AM    64
#define AKC   128
#define AST   136
#define ASTB  272
#define A_AH  0
#define A_AL  (AM * AST)
#define A_BH  (2 * AM * AST)
#define A_BL  (2 * AM * AST + NOUT * AST)
#define BUF_SHORTS (2 * AM * AST + 2 * NOUT * AST)
#define BUF_BYTES  (BUF_SHORTS * 2)
#define SMEM_A_BYTES (2 * BUF_BYTES)
#define DEC_S 97

__global__ void __launch_bounds__(256, 1) kernelA(
    const float* __restrict__ x,
    const float* __restrict__ db,
    const float* __restrict__ ntl,
    const float* __restrict__ gb,
    const int*   __restrict__ pidx,
    const float* __restrict__ pdir)
{
    extern __shared__ __align__(16) unsigned short sa[];
    __shared__ float s_invt[NDEC];
    __shared__ float s_bias[NDEC];
    __shared__ float s_gb[NT];
    __shared__ int   s_pi[NL * 3];
    __shared__ float s_pd[NL * 3];

    const int tid  = threadIdx.x;
    const int lane = tid & 31;
    const int wid  = tid >> 5;
    const int wr   = wid & 3;
    const int wc   = wid >> 2;
    const int tok0 = blockIdx.x * AM;
    const uint32_t smbase = smem_u32(sa);

    if (tid < NDEC) {
        float t  = ntl[tid] + 0.5413f;
        float sp = (t > 20.f) ? t : log1pf(__expf(t));
        s_invt[tid] = 1.0f / sp;
        s_bias[tid] = db[tid];
    } else if (tid < NDEC + NT) {
        s_gb[tid - NDEC] = gb[tid - NDEC];
    } else if (tid < NDEC + NT + NL * 3) {
        int i = tid - NDEC - NT;
        s_pi[i] = pidx[i];
        s_pd[i] = pdir[i];
    }

    const int xr  = tid >> 5;
    const int xkq = tid & 31;
    const int wrr = tid >> 4;
    const int wq  = tid & 15;

    float acc[6][4];
    #pragma unroll
    for (int n = 0; n < 6; n++)
        #pragma unroll
        for (int e = 0; e < 4; e++) acc[n][e] = 0.f;

    const uint32_t aoff = (wr * 16 + (lane & 15)) * ASTB + ((lane >> 4) & 1) * 16;
    const uint32_t boff = (wc * 48 + (lane & 7) + ((lane & 16) ? 8 : 0)) * ASTB + ((lane & 8) ? 16 : 0);

    float4 xv[8];
    #pragma unroll
    for (int it = 0; it < 8; it++) {
        int r = it * 8 + xr;
        xv[it] = *(const float4*)(x + (size_t)(tok0 + r) * DIN + xkq * 4);
    }
    #pragma unroll
    for (int it = 0; it < 6; it++) {
        int r = it * 16 + wrr;
        uint32_t dsth = smbase + (A_BH + r * AST + wq * 8) * 2;
        CP16(dsth, g_whi + (size_t)r * DIN + wq * 8);
        CP16(dsth + (NOUT * AST) * 2, g_wlo + (size_t)r * DIN + wq * 8);
    }
    CP_COMMIT();

    for (int kc = 0; kc < 8; kc++) {
        const int b = kc & 1;
        unsigned short* Ah = sa + b * BUF_SHORTS;
        unsigned short* Al = Ah + A_AL;
        const uint32_t sb = smbase + b * BUF_BYTES;

        float4 xn[8];
        if (kc < 7) {
            #pragma unroll
            for (int it = 0; it < 8; it++) {
                int r = it * 8 + xr;
                xn[it] = *(const float4*)(x + (size_t)(tok0 + r) * DIN + (kc + 1) * AKC + xkq * 4);
            }
        }

        #pragma unroll
        for (int it = 0; it < 8; it++) {
            int r = it * 8 + xr;
            ushort4 hv, lv;
            split_bf16(xv[it].x, hv.x, lv.x); split_bf16(xv[it].y, hv.y, lv.y);
            split_bf16(xv[it].z, hv.z, lv.z); split_bf16(xv[it].w, hv.w, lv.w);
            *(ushort4*)(Ah + r * AST + xkq * 4) = hv;
            *(ushort4*)(Al + r * AST + xkq * 4) = lv;
        }
        CP_WAIT0();
        __syncthreads();

        if (kc < 7) {
            const uint32_t so = smbase + (1 - b) * BUF_BYTES;
            #pragma unroll
            for (int it = 0; it < 6; it++) {
                int r = it * 16 + wrr;
                uint32_t dsth = so + (A_BH + r * AST + wq * 8) * 2;
                CP16(dsth, g_whi + (size_t)r * DIN + (kc + 1) * AKC + wq * 8);
                CP16(dsth + (NOUT * AST) * 2, g_wlo + (size_t)r * DIN + (kc + 1) * AKC + wq * 8);
            }
            CP_COMMIT();
        }

        const uint32_t aH0 = sb + aoff;
        const uint32_t aL0 = aH0 + AM * ASTB;
        const uint32_t bH0 = sb + A_BH * 2 + boff;
        const uint32_t bL0 = bH0 + NOUT * ASTB;
        #pragma unroll
        for (int ks = 0; ks < 8; ks++) {
            uint32_t ah[4], al[4];
            LDSM4(ah, aH0 + ks * 32);
            LDSM4(al, aL0 + ks * 32);
            #pragma unroll
            for (int g = 0; g < 3; g++) {
                uint32_t bh[4], bl[4];
                LDSM4(bh, bH0 + g * 16 * ASTB + ks * 32);
                LDSM4(bl, bL0 + g * 16 * ASTB + ks * 32);
                MMA16816(acc[2 * g],     ah, bh[0], bh[1]);
                MMA16816(acc[2 * g + 1], ah, bh[2], bh[3]);
                MMA16816(acc[2 * g],     ah, bl[0], bl[1]);
                MMA16816(acc[2 * g + 1], ah, bl[2], bl[3]);
                MMA16816(acc[2 * g],     al, bh[0], bh[1]);
                MMA16816(acc[2 * g + 1], al, bh[2], bh[3]);
            }
        }
        __syncthreads();

        if (kc < 7) {
            #pragma unroll
            for (int it = 0; it < 8; it++) xv[it] = xn[it];
        }
    }

    float* Dec = (float*)sa;
    const int trow = lane >> 2;
    const int tcol = (lane & 3) * 2;
    #pragma unroll
    for (int nt = 0; nt < 6; nt++) {
        int col = wc * 48 + nt * 8 + tcol;
        Dec[(wr * 16 + trow) * DEC_S + col]         = acc[nt][0];
        Dec[(wr * 16 + trow) * DEC_S + col + 1]     = acc[nt][1];
        Dec[(wr * 16 + trow + 8) * DEC_S + col]     = acc[nt][2];
        Dec[(wr * 16 + trow + 8) * DEC_S + col + 1] = acc[nt][3];
    }
    __syncthreads();

    if (tid < AM) {
        const int token = tok0 + tid;
        const float* d = Dec + tid * DEC_S;

        float g[NT];
        float m = -1e30f;
        #pragma unroll
        for (int t = 0; t < NT; t++) { g[t] = d[NDEC + t] + s_gb[t]; m = fmaxf(m, g[t]); }
        float sum = 0.f;
        #pragma unroll
        for (int t = 0; t < NT; t++) { g[t] = __expf(g[t] - m); sum += g[t]; }
        const float inv = 1.0f / sum;

        unsigned short* rh = g_rhi + (size_t)token * NOUT;
        unsigned short* rl = g_rlo + (size_t)token * NOUT;

        #pragma unroll
        for (int t = 0; t < NT; t++) {
            const float wgt = g[t] * inv;
            float sg[NI];
            #pragma unroll
            for (int n = 0; n < NI; n++) {
                float z = (d[t * NI + n] + s_bias[t * NI + n]) * s_invt[t * NI + n];
                sg[n] = 1.0f / (1.0f + __expf(-z));
            }
            #pragma unroll
            for (int l = 0; l < NL; l++) {
                float p = wgt;
                #pragma unroll
                for (int dd = 0; dd < 3; dd++) {
                    float sv  = sg[s_pi[l * 3 + dd]];
                    float dir = s_pd[l * 3 + dd];
                    p *= dir * sv + (1.f - dir) * (1.f - sv);
                }
                unsigned short hs, ls;
                split_bf16(p, hs, ls);
                rh[t * NL + l] = hs;
                rl[t * NL + l] = ls;
            }
        }
    }
}

// ---------------------------------------------------------------------------
// Kernel B (HMMA): out[h, 128 tok, 128 d] = routed[128,96] @ LO[96,128]
//   256 threads, 8 warps (4 tok-groups x 2 d-groups), warp tile 32x64
//   105KB smem -> 2 CTAs/SM for cross-CTA stage/compute/store overlap
// ---------------------------------------------------------------------------
#define BT_M  128
#define BT_N  128
#define SSTA  104                 // A row stride shorts (96+8)
#define SSTAB 208
#define SSTB  136                 // B row stride shorts (128+8)
#define SSTBB 272
#define OFFB  (2 * BT_M * SSTA * 2)            // byte offset of Bh: 53248
#define OFFBL (NOUT * SSTBB)                   // Bl rel. to Bh: 26112 bytes
#define SMEM_B_BYTES (OFFB + 2 * NOUT * SSTBB) // 105472

__global__ void __launch_bounds__(256, 2) kernelB(float* __restrict__ out) {
    extern __shared__ __align__(16) unsigned short sh[];

    const int tid  = threadIdx.x;
    const int lane = tid & 31;
    const int wid  = tid >> 5;
    const int wr   = wid & 3;     // token group (32 rows)
    const int wc   = wid >> 2;    // d group (64 cols)
    const int tok0 = blockIdx.x * BT_M;
    const int d0   = blockIdx.y * BT_N;
    const int h    = blockIdx.z;
    const uint32_t smbase = smem_u32(sh);

    // stage A: routed 128 tok x 96 l (hi+lo): 1536 x 16B each
    #pragma unroll
    for (int i = tid; i < BT_M * 12; i += 256) {
        int r = i / 12, q = i - r * 12;
        size_t src = (size_t)(tok0 + r) * 192 + q * 16;     // bytes
        uint32_t dst = smbase + r * SSTAB + q * 16;
        CP16(dst, (const char*)g_rhi + src);
        CP16(dst + BT_M * SSTAB, (const char*)g_rlo + src);
    }
    // stage B: LO 96 l x 128 d (hi+lo): 1536 x 16B each
    #pragma unroll
    for (int i = tid; i < NOUT * 16; i += 256) {
        int r = i >> 4, q = i & 15;
        size_t src = ((size_t)(h * NOUT + r) * DOUTD + d0 + q * 8) * 2;  // bytes
        uint32_t dst = smbase + OFFB + r * SSTBB + q * 16;
        CP16(dst, (const char*)g_bhi + src);
        CP16(dst + OFFBL, (const char*)g_blo + src);
    }
    CP_COMMIT();
    CP_WAIT0();
    __syncthreads();

    const uint32_t aH0 = smbase + (wr * 32 + (lane & 15)) * SSTAB + ((lane >> 4) & 1) * 16;
    const uint32_t aL0 = aH0 + BT_M * SSTAB;
    const uint32_t bH0 = smbase + OFFB + (lane & 15) * SSTBB + (wc * 64 + ((lane >> 4) & 1) * 8) * 2;
    const uint32_t bL0 = bH0 + OFFBL;

    float acc[2][8][4];
    #pragma unroll
    for (int m = 0; m < 2; m++)
        #pragma unroll
        for (int n = 0; n < 8; n++)
            #pragma unroll
            for (int e = 0; e < 4; e++) acc[m][n][e] = 0.f;

    #pragma unroll
    for (int ks = 0; ks < 6; ks++) {
        uint32_t ah[2][4], al[2][4];
        #pragma unroll
        for (int mt = 0; mt < 2; mt++) {
            LDSM4(ah[mt], aH0 + mt * 16 * SSTAB + ks * 32);
            LDSM4(al[mt], aL0 + mt * 16 * SSTAB + ks * 32);
        }
        #pragma unroll
        for (int g = 0; g < 4; g++) {
            uint32_t bh[4], bl[4];
            LDSM4T(bh, bH0 + g * 32 + ks * 16 * SSTBB);
            LDSM4T(bl, bL0 + g * 32 + ks * 16 * SSTBB);
            #pragma unroll
            for (int mt = 0; mt < 2; mt++) {
                MMA16816(acc[mt][2 * g],     ah[mt], bh[0], bh[1]);
                MMA16816(acc[mt][2 * g + 1], ah[mt], bh[2], bh[3]);
                MMA16816(acc[mt][2 * g],     ah[mt], bl[0], bl[1]);
                MMA16816(acc[mt][2 * g + 1], ah[mt], bl[2], bl[3]);
                MMA16816(acc[mt][2 * g],     al[mt], bh[0], bh[1]);
                MMA16816(acc[mt][2 * g + 1], al[mt], bh[2], bh[3]);
            }
        }
    }

    const int trow = lane >> 2;
    const int tcol = (lane & 3) * 2;
    #pragma unroll
    for (int mt = 0; mt < 2; mt++) {
        int tokb = tok0 + wr * 32 + mt * 16 + trow;
        float* ob0 = out + ((size_t)h * NTOK + tokb) * DOUTD + d0 + wc * 64 + tcol;
        float* ob1 = ob0 + 8 * DOUTD;
        #pragma unroll
        for (int nt = 0; nt < 8; nt++) {
            *(float2*)(ob0 + nt * 8) = make_float2(acc[mt][nt][0], acc[mt][nt][1]);
            *(float2*)(ob1 + nt * 8) = make_float2(acc[mt][nt][2], acc[mt][nt][3]);
        }
    }
}

// ---------------------------------------------------------------------------
extern "C" void kernel_launch(void* const* d_in, const int* in_sizes, int n_in,
                              void* d_out, int out_size) {
    const float* x    = (const float*)d_in[0];
    const float* dw   = (const float*)d_in[1];
    const float* db   = (const float*)d_in[2];
    const float* ntl  = (const float*)d_in[3];
    const float* gw   = (const float*)d_in[4];
    const float* gb   = (const float*)d_in[5];
    const float* lo   = (const float*)d_in[6];
    const int*   pidx = (const int*)d_in[7];
    const float* pdir = (const float*)d_in[8];
    float* out = (float*)d_out;

    cudaFuncSetAttribute(kernelA, cudaFuncAttributeMaxDynamicSharedMemorySize, SMEM_A_BYTES);
    cudaFuncSetAttribute(kernelB, cudaFuncAttributeMaxDynamicSharedMemorySize, SMEM_B_BYTES);

    kernelW<<<96, 256>>>(dw, gw);
    kernelA<<<NTOK / AM, 256, SMEM_A_BYTES>>>(x, db, ntl, gb, pidx, pdir);
    kernelLO<<<288, 256>>>(lo);

    dim3 gridB(NTOK / BT_M, DOUTD / BT_N, NHEADS);
    kernelB<<<gridB, 256, SMEM_B_BYTES>>>(out);
}

// round 7
// speedup vs baseline: 1.9053x; 1.0035x over previous
#include <cuda_runtime.h>
#include <cuda_bf16.h>
#include <math.h>
#include <stdint.h>

// Problem constants
#define NTOK   8192
#define DIN    1024
#define NT     12
#define NI     7
#define NL     8
#define NDEC   84
#define NOUT   96
#define DOUTD  1024
#define NHEADS 3

// ---------------- scratch (device globals) ----------------
__device__ __align__(16) unsigned short g_rhi[NTOK * NOUT];           // routed hi bf16 [tok][96]
__device__ __align__(16) unsigned short g_rlo[NTOK * NOUT];           // routed lo
__device__ __align__(16) unsigned short g_bhi[NHEADS * NOUT * DOUTD]; // LO hi  [h][l][d]
__device__ __align__(16) unsigned short g_blo[NHEADS * NOUT * DOUTD]; // LO lo
__device__ __align__(16) unsigned short g_whi[NOUT * DIN];            // W hi   [96][1024]
__device__ __align__(16) unsigned short g_wlo[NOUT * DIN];            // W lo

__device__ __forceinline__ uint32_t smem_u32(const void* p) {
    uint32_t a;
    asm("{ .reg .u64 t; cvta.to.shared.u64 t, %1; cvt.u32.u64 %0, t; }" : "=r"(a) : "l"(p));
    return a;
}
__device__ __forceinline__ void split_bf16(float x, unsigned short &h, unsigned short &l) {
    __nv_bfloat16 hb = __float2bfloat16(x);
    float hf = __bfloat162float(hb);
    __nv_bfloat16 lb = __float2bfloat16(x - hf);
    h = __bfloat16_as_ushort(hb);
    l = __bfloat16_as_ushort(lb);
}

// ---------------- mma.sync / ldmatrix / cp.async ----------------
#define LDSM4(r, addr) \
    asm volatile("ldmatrix.sync.aligned.m8n8.x4.shared.b16 {%0,%1,%2,%3}, [%4];" \
        : "=r"((r)[0]), "=r"((r)[1]), "=r"((r)[2]), "=r"((r)[3]) : "r"(addr))

#define LDSM4T(r, addr) \
    asm volatile("ldmatrix.sync.aligned.m8n8.x4.trans.shared.b16 {%0,%1,%2,%3}, [%4];" \
        : "=r"((r)[0]), "=r"((r)[1]), "=r"((r)[2]), "=r"((r)[3]) : "r"(addr))

#define MMA16816(c, a, b0, b1) \
    asm volatile("mma.sync.aligned.m16n8k16.row.col.f32.bf16.bf16.f32 " \
        "{%0,%1,%2,%3}, {%4,%5,%6,%7}, {%8,%9}, {%0,%1,%2,%3};" \
        : "+f"((c)[0]), "+f"((c)[1]), "+f"((c)[2]), "+f"((c)[3]) \
        : "r"((a)[0]), "r"((a)[1]), "r"((a)[2]), "r"((a)[3]), "r"(b0), "r"(b1))

#define CP16(sm, gm) \
    asm volatile("cp.async.cg.shared.global [%0], [%1], 16;" :: "r"(sm), "l"(gm))
#define CP_COMMIT() asm volatile("cp.async.commit_group;" ::: "memory")
#define CP_WAIT0()  asm volatile("cp.async.wait_group 0;" ::: "memory")
#define CP_WAIT1()  asm volatile("cp.async.wait_group 1;" ::: "memory")

// ---------------------------------------------------------------------------
// Kernel W: convert W [96][1024] fp32 -> bf16 hi/lo
// ---------------------------------------------------------------------------
__global__ void __launch_bounds__(256) kernelW(
    const float* __restrict__ dw, const float* __restrict__ gw)
{
    int widx = blockIdx.x * 256 + threadIdx.x;   // < 24576
    int o  = widx >> 8;
    int kq = widx & 255;
    const float* src = (o < NDEC) ? (dw + (size_t)o * DIN) : (gw + (size_t)(o - NDEC) * DIN);
    float4 v = *(const float4*)(src + kq * 4);
    ushort4 hv, lv;
    split_bf16(v.x, hv.x, lv.x); split_bf16(v.y, hv.y, lv.y);
    split_bf16(v.z, hv.z, lv.z); split_bf16(v.w, hv.w, lv.w);
    *(ushort4*)(g_whi + (size_t)o * DIN + kq * 4) = hv;
    *(ushort4*)(g_wlo + (size_t)o * DIN + kq * 4) = lv;
}

// ---------------------------------------------------------------------------
// Kernel LO: convert leaf_outputs [h][l][d] fp32 -> bf16 hi/lo (coalesced)
// ---------------------------------------------------------------------------
__global__ void __launch_bounds__(256) kernelLO(const float* __restrict__ lo) {
    int idx = blockIdx.x * 256 + threadIdx.x;    // < 73728 float4
    float4 v = ((const float4*)lo)[idx];
    ushort4 hv, lv;
    split_bf16(v.x, hv.x, lv.x); split_bf16(v.y, hv.y, lv.y);
    split_bf16(v.z, hv.z, lv.z); split_bf16(v.w, hv.w, lv.w);
    *(ushort4*)(g_bhi + (size_t)idx * 4) = hv;
    *(ushort4*)(g_blo + (size_t)idx * 4) = lv;
}

// ---------------------------------------------------------------------------
// Kernel A (HMMA, double-buffered): decisions[64,96] = x[64,1024] @ W^T
// ---------------------------------------------------------------------------
#define AM    64
#define AKC   128
#define AST   136
#define ASTB  272
#define A_AH  0
#define A_AL  (AM * AST)
#define A_BH  (2 * AM * AST)
#define A_BL  (2 * AM * AST + NOUT * AST)
#define BUF_SHORTS (2 * AM * AST + 2 * NOUT * AST)
#define BUF_BYTES  (BUF_SHORTS * 2)
#define SMEM_A_BYTES (2 * BUF_BYTES)
#define DEC_S 97

__global__ void __launch_bounds__(256, 1) kernelA(
    const float* __restrict__ x,
    const float* __restrict__ db,
    const float* __restrict__ ntl,
    const float* __restrict__ gb,
    const int*   __restrict__ pidx,
    const float* __restrict__ pdir)
{
    extern __shared__ __align__(16) unsigned short sa[];
    __shared__ float s_invt[NDEC];
    __shared__ float s_bias[NDEC];
    __shared__ float s_gb[NT];
    __shared__ int   s_pi[NL * 3];
    __shared__ float s_pd[NL * 3];

    const int tid  = threadIdx.x;
    const int lane = tid & 31;
    const int wid  = tid >> 5;
    const int wr   = wid & 3;
    const int wc   = wid >> 2;
    const int tok0 = blockIdx.x * AM;
    const uint32_t smbase = smem_u32(sa);

    if (tid < NDEC) {
        float t  = ntl[tid] + 0.5413f;
        float sp = (t > 20.f) ? t : log1pf(__expf(t));
        s_invt[tid] = 1.0f / sp;
        s_bias[tid] = db[tid];
    } else if (tid < NDEC + NT) {
        s_gb[tid - NDEC] = gb[tid - NDEC];
    } else if (tid < NDEC + NT + NL * 3) {
        int i = tid - NDEC - NT;
        s_pi[i] = pidx[i];
        s_pd[i] = pdir[i];
    }

    const int xr  = tid >> 5;
    const int xkq = tid & 31;
    const int wrr = tid >> 4;
    const int wq  = tid & 15;

    float acc[6][4];
    #pragma unroll
    for (int n = 0; n < 6; n++)
        #pragma unroll
        for (int e = 0; e < 4; e++) acc[n][e] = 0.f;

    const uint32_t aoff = (wr * 16 + (lane & 15)) * ASTB + ((lane >> 4) & 1) * 16;
    const uint32_t boff = (wc * 48 + (lane & 7) + ((lane & 16) ? 8 : 0)) * ASTB + ((lane & 8) ? 16 : 0);

    float4 xv[8];
    #pragma unroll
    for (int it = 0; it < 8; it++) {
        int r = it * 8 + xr;
        xv[it] = *(const float4*)(x + (size_t)(tok0 + r) * DIN + xkq * 4);
    }
    #pragma unroll
    for (int it = 0; it < 6; it++) {
        int r = it * 16 + wrr;
        uint32_t dsth = smbase + (A_BH + r * AST + wq * 8) * 2;
        CP16(dsth, g_whi + (size_t)r * DIN + wq * 8);
        CP16(dsth + (NOUT * AST) * 2, g_wlo + (size_t)r * DIN + wq * 8);
    }
    CP_COMMIT();

    for (int kc = 0; kc < 8; kc++) {
        const int b = kc & 1;
        unsigned short* Ah = sa + b * BUF_SHORTS;
        unsigned short* Al = Ah + A_AL;
        const uint32_t sb = smbase + b * BUF_BYTES;

        float4 xn[8];
        if (kc < 7) {
            #pragma unroll
            for (int it = 0; it < 8; it++) {
                int r = it * 8 + xr;
                xn[it] = *(const float4*)(x + (size_t)(tok0 + r) * DIN + (kc + 1) * AKC + xkq * 4);
            }
        }

        #pragma unroll
        for (int it = 0; it < 8; it++) {
            int r = it * 8 + xr;
            ushort4 hv, lv;
            split_bf16(xv[it].x, hv.x, lv.x); split_bf16(xv[it].y, hv.y, lv.y);
            split_bf16(xv[it].z, hv.z, lv.z); split_bf16(xv[it].w, hv.w, lv.w);
            *(ushort4*)(Ah + r * AST + xkq * 4) = hv;
            *(ushort4*)(Al + r * AST + xkq * 4) = lv;
        }
        CP_WAIT0();
        __syncthreads();

        if (kc < 7) {
            const uint32_t so = smbase + (1 - b) * BUF_BYTES;
            #pragma unroll
            for (int it = 0; it < 6; it++) {
                int r = it * 16 + wrr;
                uint32_t dsth = so + (A_BH + r * AST + wq * 8) * 2;
                CP16(dsth, g_whi + (size_t)r * DIN + (kc + 1) * AKC + wq * 8);
                CP16(dsth + (NOUT * AST) * 2, g_wlo + (size_t)r * DIN + (kc + 1) * AKC + wq * 8);
            }
            CP_COMMIT();
        }

        const uint32_t aH0 = sb + aoff;
        const uint32_t aL0 = aH0 + AM * ASTB;
        const uint32_t bH0 = sb + A_BH * 2 + boff;
        const uint32_t bL0 = bH0 + NOUT * ASTB;
        #pragma unroll
        for (int ks = 0; ks < 8; ks++) {
            uint32_t ah[4], al[4];
            LDSM4(ah, aH0 + ks * 32);
            LDSM4(al, aL0 + ks * 32);
            #pragma unroll
            for (int g = 0; g < 3; g++) {
                uint32_t bh[4], bl[4];
                LDSM4(bh, bH0 + g * 16 * ASTB + ks * 32);
                LDSM4(bl, bL0 + g * 16 * ASTB + ks * 32);
                MMA16816(acc[2 * g],     ah, bh[0], bh[1]);
                MMA16816(acc[2 * g + 1], ah, bh[2], bh[3]);
                MMA16816(acc[2 * g],     ah, bl[0], bl[1]);
                MMA16816(acc[2 * g + 1], ah, bl[2], bl[3]);
                MMA16816(acc[2 * g],     al, bh[0], bh[1]);
                MMA16816(acc[2 * g + 1], al, bh[2], bh[3]);
            }
        }
        __syncthreads();

        if (kc < 7) {
            #pragma unroll
            for (int it = 0; it < 8; it++) xv[it] = xn[it];
        }
    }

    float* Dec = (float*)sa;
    const int trow = lane >> 2;
    const int tcol = (lane & 3) * 2;
    #pragma unroll
    for (int nt = 0; nt < 6; nt++) {
        int col = wc * 48 + nt * 8 + tcol;
        Dec[(wr * 16 + trow) * DEC_S + col]         = acc[nt][0];
        Dec[(wr * 16 + trow) * DEC_S + col + 1]     = acc[nt][1];
        Dec[(wr * 16 + trow + 8) * DEC_S + col]     = acc[nt][2];
        Dec[(wr * 16 + trow + 8) * DEC_S + col + 1] = acc[nt][3];
    }
    __syncthreads();

    if (tid < AM) {
        const int token = tok0 + tid;
        const float* d = Dec + tid * DEC_S;

        float g[NT];
        float m = -1e30f;
        #pragma unroll
        for (int t = 0; t < NT; t++) { g[t] = d[NDEC + t] + s_gb[t]; m = fmaxf(m, g[t]); }
        float sum = 0.f;
        #pragma unroll
        for (int t = 0; t < NT; t++) { g[t] = __expf(g[t] - m); sum += g[t]; }
        const float inv = 1.0f / sum;

        unsigned short* rh = g_rhi + (size_t)token * NOUT;
        unsigned short* rl = g_rlo + (size_t)token * NOUT;

        #pragma unroll
        for (int t = 0; t < NT; t++) {
            const float wgt = g[t] * inv;
            float sg[NI];
            #pragma unroll
            for (int n = 0; n < NI; n++) {
                float z = (d[t * NI + n] + s_bias[t * NI + n]) * s_invt[t * NI + n];
                sg[n] = 1.0f / (1.0f + __expf(-z));
            }
            #pragma unroll
            for (int l = 0; l < NL; l++) {
                float p = wgt;
                #pragma unroll
                for (int dd = 0; dd < 3; dd++) {
                    float sv  = sg[s_pi[l * 3 + dd]];
                    float dir = s_pd[l * 3 + dd];
                    p *= dir * sv + (1.f - dir) * (1.f - sv);
                }
                unsigned short hs, ls;
                split_bf16(p, hs, ls);
                rh[t * NL + l] = hs;
                rl[t * NL + l] = ls;
            }
        }
    }
}

// ---------------------------------------------------------------------------
// Kernel B v2 (HMMA, d-looped, double-buffered LO tiles):
//   CTA = (64 tokens, head), loops 4 d-tiles of 256.
//   A (routed) staged once: padded rows (208B stride, conflict-free LDSM).
//   B (LO) tiles: unpadded 512B rows with 16B-chunk XOR swizzle, cp.async
//   double-buffered so next tile flies during current tile's MMA.
//   8 warps: wr (2 x 32 tok) x wc (4 x 64 d); warp tile 32x64.
// ---------------------------------------------------------------------------
#define BM 64
#define BN 256
#define BSTAB   208                    // A row stride bytes (104 shorts)
#define AB_SZ   (2 * BM * BSTAB)       // A hi+lo: 26624
#define BDT_SZ  (NOUT * 512)           // one dtype B tile: 49152
#define BBUF_SZ (2 * BDT_SZ)           // hi+lo: 98304
#define SMEM_B_BYTES (1024 + AB_SZ + 2 * BBUF_SZ)   // 224256

__device__ __forceinline__ void stageB(uint32_t bbase, int h, int d0, int tid) {
    // 96 rows x 32 chunks(16B) per dtype; 3072 chunks / 256 thr = 12 each
    #pragma unroll
    for (int p = 0; p < 12; p++) {
        int i = p * 256 + tid;
        int r = i >> 5, q = i & 31;
        uint32_t dst = bbase + r * 512 + ((q ^ (r & 7)) << 4);
        size_t src = ((size_t)(h * NOUT + r) * DOUTD + d0 + q * 8) * 2;  // bytes
        CP16(dst,           (const char*)g_bhi + src);
        CP16(dst + BDT_SZ,  (const char*)g_blo + src);
    }
}

__global__ void __launch_bounds__(256, 1) kernelB(float* __restrict__ out) {
    extern __shared__ __align__(16) unsigned char shb[];
    const uint32_t raw   = smem_u32(shb);
    const uint32_t abase = (raw + 1023u) & ~1023u;
    const uint32_t bbase = abase + AB_SZ;

    const int tid  = threadIdx.x;
    const int lane = tid & 31;
    const int wid  = tid >> 5;
    const int wr   = wid & 1;      // 2 token groups of 32
    const int wc   = wid >> 1;     // 4 d groups of 64
    const int tok0 = blockIdx.x * BM;
    const int h    = blockIdx.y;

    // ---- stage A once (768 chunks per dtype / 256 thr = 3 each) ----
    #pragma unroll
    for (int p = 0; p < 3; p++) {
        int i = p * 256 + tid;
        int r = i / 12, q = i - r * 12;
        uint32_t dst = abase + r * BSTAB + q * 16;
        size_t src = ((size_t)(tok0 + r) * NOUT + q * 8) * 2;   // bytes
        CP16(dst,               (const char*)g_rhi + src);
        CP16(dst + BM * BSTAB,  (const char*)g_rlo + src);
    }
    stageB(bbase, h, 0, tid);
    CP_COMMIT();                       // group0: A + Btile0
    stageB(bbase + BBUF_SZ, h, 256, tid);
    CP_COMMIT();                       // group1: Btile1

    // per-lane LDSM address components
    const uint32_t aoff = (wr * 32 + (lane & 15)) * BSTAB + ((lane >> 4) & 1) * 16;
    const int  brow   = lane & 15;                      // k-row within ks block
    const int  bsw    = lane & 7;                       // swizzle XOR (row&7)
    const int  q00    = wc * 8 + ((lane >> 4) & 1);     // base 16B-chunk index

    for (int it = 0; it < 4; it++) {
        if (it == 3) { CP_WAIT0(); } else { CP_WAIT1(); }
        __syncthreads();

        const uint32_t bb = bbase + (it & 1) * BBUF_SZ;
        const int d0 = it * BN;

        float acc[2][8][4];
        #pragma unroll
        for (int m = 0; m < 2; m++)
            #pragma unroll
            for (int n = 0; n < 8; n++)
                #pragma unroll
                for (int e = 0; e < 4; e++) acc[m][n][e] = 0.f;

        #pragma unroll
        for (int ks = 0; ks < 6; ks++) {
            uint32_t ah[2][4], al[2][4];
            const uint32_t aH0 = abase + aoff + ks * 32;
            #pragma unroll
            for (int mt = 0; mt < 2; mt++) {
                LDSM4(ah[mt], aH0 + mt * 16 * BSTAB);
                LDSM4(al[mt], aH0 + mt * 16 * BSTAB + BM * BSTAB);
            }
            const uint32_t brb = bb + (ks * 16 + brow) * 512;
            #pragma unroll
            for (int g = 0; g < 4; g++) {
                uint32_t bh[4], bl[4];
                uint32_t baddr = brb + (((q00 + g * 2) ^ bsw) << 4);
                LDSM4T(bh, baddr);
                LDSM4T(bl, baddr + BDT_SZ);
                #pragma unroll
                for (int mt = 0; mt < 2; mt++) {
                    MMA16816(acc[mt][2 * g],     ah[mt], bh[0], bh[1]);
                    MMA16816(acc[mt][2 * g + 1], ah[mt], bh[2], bh[3]);
                    MMA16816(acc[mt][2 * g],     ah[mt], bl[0], bl[1]);
                    MMA16816(acc[mt][2 * g + 1], ah[mt], bl[2], bl[3]);
                    MMA16816(acc[mt][2 * g],     al[mt], bh[0], bh[1]);
                    MMA16816(acc[mt][2 * g + 1], al[mt], bh[2], bh[3]);
                }
            }
        }

        // store this d-tile
        const int trow = lane >> 2;
        const int tcol = (lane & 3) * 2;
        #pragma unroll
        for (int mt = 0; mt < 2; mt++) {
            int tokb = tok0 + wr * 32 + mt * 16 + trow;
            float* ob0 = out + ((size_t)h * NTOK + tokb) * DOUTD + d0 + wc * 64 + tcol;
            float* ob1 = ob0 + 8 * DOUTD;
            #pragma unroll
            for (int nt = 0; nt < 8; nt++) {
                *(float2*)(ob0 + nt * 8) = make_float2(acc[mt][nt][0], acc[mt][nt][1]);
                *(float2*)(ob1 + nt * 8) = make_float2(acc[mt][nt][2], acc[mt][nt][3]);
            }
        }

        __syncthreads();   // everyone done reading buf (it&1) before refill
        if (it < 2) {
            stageB(bbase + (it & 1) * BBUF_SZ, h, (it + 2) * BN, tid);
            CP_COMMIT();
        }
    }
}

// ---------------------------------------------------------------------------
extern "C" void kernel_launch(void* const* d_in, const int* in_sizes, int n_in,
                              void* d_out, int out_size) {
    const float* x    = (const float*)d_in[0];
    const float* dw   = (const float*)d_in[1];
    const float* db   = (const float*)d_in[2];
    const float* ntl  = (const float*)d_in[3];
    const float* gw   = (const float*)d_in[4];
    const float* gb   = (const float*)d_in[5];
    const float* lo   = (const float*)d_in[6];
    const int*   pidx = (const int*)d_in[7];
    const float* pdir = (const float*)d_in[8];
    float* out = (float*)d_out;

    cudaFuncSetAttribute(kernelA, cudaFuncAttributeMaxDynamicSharedMemorySize, SMEM_A_BYTES);
    cudaFuncSetAttribute(kernelB, cudaFuncAttributeMaxDynamicSharedMemorySize, SMEM_B_BYTES);

    kernelW<<<96, 256>>>(dw, gw);
    kernelA<<<NTOK / AM, 256, SMEM_A_BYTES>>>(x, db, ntl, gb, pidx, pdir);
    kernelLO<<<288, 256>>>(lo);

    dim3 gridB(NTOK / BM, NHEADS);
    kernelB<<<gridB, 256, SMEM_B_BYTES>>>(out);
}